// round 6
// baseline (speedup 1.0000x reference)
#include <cuda_runtime.h>
#include <cuda_bf16.h>
#include <math.h>

#define CIN   256
#define HH    64
#define WW    64
#define NPIX  4096
#define BATCH 32
#define KPTS  17

typedef unsigned short ushort_t;
typedef unsigned int   uint_t;

// ---------------------------------------------------------------------------
// Scratch (device globals — no runtime allocation allowed)
// Activations NHWC hi/lo: addr = (n*4096 + p)*C + ci
// ---------------------------------------------------------------------------
__device__ __align__(1024) ushort_t g_xh[33554432];
__device__ __align__(1024) ushort_t g_xl[33554432];
__device__ __align__(1024) ushort_t g_ah[33554432];
__device__ __align__(1024) ushort_t g_al[33554432];
__device__ __align__(1024) ushort_t g_sh[33554432];
__device__ __align__(1024) ushort_t g_sl[33554432];
__device__ __align__(1024) ushort_t g_th[33554432];
__device__ __align__(1024) ushort_t g_tl[33554432];
__device__ __align__(1024) ushort_t g_wh[2654208];
__device__ __align__(1024) ushort_t g_wl[2654208];

// ---------------------------------------------------------------------------
__device__ __forceinline__ unsigned smem_to_u32(const void* p) {
    unsigned a;
    asm("{ .reg .u64 t; cvta.to.shared.u64 t, %1; cvt.u32.u64 %0, t; }"
        : "=r"(a) : "l"(p));
    return a;
}
__device__ __forceinline__ ushort_t f2h(float v) {
    __nv_bfloat16 b = __float2bfloat16(v);
    return *(ushort_t*)&b;
}
__device__ __forceinline__ float h2f(ushort_t u) {
    __nv_bfloat16 b = *(__nv_bfloat16*)&u;
    return __bfloat162float(b);
}
__device__ __forceinline__ void ldmatrix_x4(uint_t* r, unsigned addr) {
    asm volatile("ldmatrix.sync.aligned.m8n8.x4.shared.b16 {%0,%1,%2,%3}, [%4];"
                 : "=r"(r[0]), "=r"(r[1]), "=r"(r[2]), "=r"(r[3]) : "r"(addr));
}
__device__ __forceinline__ void mma16816(float* c, const uint_t* a, const uint_t* b) {
    asm volatile(
        "mma.sync.aligned.m16n8k16.row.col.f32.bf16.bf16.f32 "
        "{%0,%1,%2,%3}, {%4,%5,%6,%7}, {%8,%9}, {%0,%1,%2,%3};"
        : "+f"(c[0]), "+f"(c[1]), "+f"(c[2]), "+f"(c[3])
        : "r"(a[0]), "r"(a[1]), "r"(a[2]), "r"(a[3]), "r"(b[0]), "r"(b[1]));
}
__device__ __forceinline__ void cp16(unsigned dst, const void* src, unsigned sz) {
    asm volatile("cp.async.cg.shared.global [%0], [%1], 16, %2;"
                 :: "r"(dst), "l"(src), "r"(sz) : "memory");
}
__device__ __forceinline__ void cp_commit() {
    asm volatile("cp.async.commit_group;" ::: "memory");
}

// ---------------------------------------------------------------------------
// NCHW fp32 -> NHWC bf16 hi/lo split (tiled 32x32 transpose)
// ---------------------------------------------------------------------------
__global__ __launch_bounds__(256) void nchw2nhwc_split(
    const float* __restrict__ x, ushort_t* __restrict__ h,
    ushort_t* __restrict__ l)
{
    __shared__ float t[32][33];
    const int n  = blockIdx.y;
    const int cb = blockIdx.x >> 7;     // 8 ci blocks of 32
    const int pb = blockIdx.x & 127;    // 128 p blocks of 32
    const int lane = threadIdx.x & 31, wr = threadIdx.x >> 5;

    const float* src = x + ((size_t)n * 256 + cb * 32) * 4096 + pb * 32;
#pragma unroll
    for (int j = 0; j < 4; j++) {
        const int ci = wr * 4 + j;
        t[ci][lane] = src[(size_t)ci * 4096 + lane];
    }
    __syncthreads();
#pragma unroll
    for (int j = 0; j < 4; j++) {
        const int p = wr * 4 + j;
        const float v = t[lane][p];
        const ushort_t hb = f2h(v);
        const size_t o = ((size_t)n * 4096 + pb * 32 + p) * 256 + cb * 32 + lane;
        h[o] = hb;
        l[o] = f2h(v - h2f(hb));
    }
}

// ---------------------------------------------------------------------------
// Weight prep: reorder w[co][ci][ky][kx] into 36 chunk-tiles (cc = cb*9 + s),
// each [co][64 ci] K-major with SW128 swizzle baked in, hi/lo split.
// ---------------------------------------------------------------------------
__global__ __launch_bounds__(256) void wprep(
    const float* __restrict__ w, ushort_t* __restrict__ wh,
    ushort_t* __restrict__ wl, int CO)
{
    int idx = blockIdx.x * 256 + threadIdx.x;   // < CO*2304 (exact multiple)
    int co = idx / 2304, r = idx % 2304;
    int ci = r / 9, s = r % 9;
    int cb = ci >> 6, cii = ci & 63;
    int cc = cb * 9 + s;
    unsigned off = (unsigned)(co * 128 + cii * 2) ^ (unsigned)((co & 7) << 4);
    size_t dst = (size_t)cc * CO * 64 + (off >> 1);
    float v = w[idx];
    ushort_t hb = f2h(v);
    wh[dst] = hb;
    wl[dst] = f2h(v - h2f(hb));
}

// ---------------------------------------------------------------------------
// cp.async stage issue for chunk cc into stage st.
// Stage layout (48KB): A_H 16K | A_L 16K | B_H 8K | B_L 8K
// ---------------------------------------------------------------------------
template <int COUT>
__device__ __forceinline__ void issue_chunk(
    int cc, int st, unsigned sb, int tid, int plane, int px, int prow, int pcol,
    unsigned swz, int n, int z,
    const ushort_t* __restrict__ act,
    const ushort_t* __restrict__ wh, const ushort_t* __restrict__ wl)
{
    const int cb = cc / 9, s = cc - cb * 9;
    const int ky = s / 3, kx = s - ky * 3;
    const int row = prow + ky - 1, col = pcol + kx - 1;
    const bool ok = (row >= 0) && (row < HH) && (col >= 0) && (col < WW);
    const ushort_t* srcA =
        act + ((size_t)(n * 4096 + (ok ? row * 64 + col : 0))) * 256 + cb * 64;
    const unsigned sz = ok ? 16u : 0u;
    const unsigned dstA = sb + st * 49152 + plane * 16384;
#pragma unroll
    for (int g = 0; g < 8; g++)
        cp16(dstA + (((unsigned)(px * 128 + g * 16)) ^ swz), srcA + g * 8, sz);

    // B: 2 hi + 2 lo 16B chunks per thread (pre-swizzled, contiguous copy)
    const size_t wbase = (size_t)cc * COUT * 64 + (size_t)z * 4096 + (size_t)tid * 16;
    const unsigned dstB = sb + st * 49152 + 32768;
    cp16(dstB + tid * 32,            wh + wbase,     16);
    cp16(dstB + tid * 32 + 16,       wh + wbase + 8, 16);
    cp16(dstB + 8192 + tid * 32,     wl + wbase,     16);
    cp16(dstB + 8192 + tid * 32 + 16,wl + wbase + 8, 16);
    cp_commit();
}

// ---------------------------------------------------------------------------
// 3x3 SAME conv + BN + ReLU, bf16 hi/lo 3-pass mma.sync, NHWC, cp.async pipe.
// CTA: M=128 pixels (2 rows x 64 cols) x N=64 couts. 8 warps = 4(M) x 2(N).
// grid = (32 tiles, 32 batch, COUT/64).
// ---------------------------------------------------------------------------
template <int COUT>
__global__ __launch_bounds__(256, 2) void conv3x3_mma(
    const ushort_t* __restrict__ inh, const ushort_t* __restrict__ inl,
    const ushort_t* __restrict__ wh,  const ushort_t* __restrict__ wl,
    const float* __restrict__ gma, const float* __restrict__ bta,
    ushort_t* __restrict__ outh, ushort_t* __restrict__ outl)
{
    extern __shared__ __align__(1024) char smem[];
    const unsigned sb = smem_to_u32(smem);
    const int tid = threadIdx.x, wid = tid >> 5, lane = tid & 31;
    const int n = blockIdx.y, r0 = blockIdx.x * 2, z = blockIdx.z;

    const int warp_m = wid & 3;   // 4 groups of 32 pixels
    const int warp_n = wid >> 2;  // 2 groups of 32 couts

    // A-build thread coords (threads 0-127: hi plane, 128-255: lo plane)
    const int plane = tid >> 7;
    const int px    = tid & 127;
    const int prow  = r0 + (px >> 6), pcol = px & 63;
    const unsigned swz = (unsigned)((px & 7) << 4);
    const ushort_t* act = plane ? inl : inh;

    float acc[2][4][4];
#pragma unroll
    for (int mt = 0; mt < 2; mt++)
#pragma unroll
        for (int nt = 0; nt < 4; nt++)
#pragma unroll
            for (int c = 0; c < 4; c++) acc[mt][nt][c] = 0.f;

    issue_chunk<COUT>(0, 0, sb, tid, plane, px, prow, pcol, swz, n, z, act, wh, wl);

    for (int cc = 0; cc < 36; cc++) {
        const int cur = cc & 1;
        if (cc < 35) {
            issue_chunk<COUT>(cc + 1, cur ^ 1, sb, tid, plane, px, prow, pcol,
                              swz, n, z, act, wh, wl);
            asm volatile("cp.async.wait_group 1;" ::: "memory");
        } else {
            asm volatile("cp.async.wait_group 0;" ::: "memory");
        }
        __syncthreads();

        const unsigned ab = sb + cur * 49152;
        const unsigned bb = ab + 32768;
#pragma unroll
        for (int k4 = 0; k4 < 4; k4++) {
            const unsigned kb = (unsigned)(k4 * 32);
            uint_t Ah[2][4], Al[2][4], Bh[4][2], Bl[4][2];
            // B loads: ldmatrix.x4 covers 2 nt tiles (k0-7 + k8-15) per call
            {
                const int j = lane & 7, g = lane >> 3;
                const int ntp = g >> 1, kh = g & 1;
#pragma unroll
                for (int q = 0; q < 2; q++) {
                    const unsigned row = (unsigned)(warp_n * 32 + (q * 2 + ntp) * 8 + j);
                    const unsigned off = (row * 128 + kb + (unsigned)(kh * 16))
                                         ^ ((unsigned)j << 4);
                    uint_t r[4];
                    ldmatrix_x4(r, bb + off);
                    Bh[q*2][0] = r[0]; Bh[q*2][1] = r[1];
                    Bh[q*2+1][0] = r[2]; Bh[q*2+1][1] = r[3];
                    ldmatrix_x4(r, bb + 8192 + off);
                    Bl[q*2][0] = r[0]; Bl[q*2][1] = r[1];
                    Bl[q*2+1][0] = r[2]; Bl[q*2+1][1] = r[3];
                }
            }
#pragma unroll
            for (int mt = 0; mt < 2; mt++) {
                const unsigned arow = (unsigned)(warp_m * 32 + mt * 16 + (lane & 15));
                const unsigned off = (arow * 128 + kb + (unsigned)((lane >> 4) << 4))
                                     ^ ((arow & 7) << 4);
                ldmatrix_x4(Ah[mt], ab + off);
                ldmatrix_x4(Al[mt], ab + 16384 + off);
            }
#pragma unroll
            for (int mt = 0; mt < 2; mt++)
#pragma unroll
                for (int nt = 0; nt < 4; nt++) {
                    mma16816(acc[mt][nt], Ah[mt], Bh[nt]);   // Ah*Bh
                    mma16816(acc[mt][nt], Ah[mt], Bl[nt]);   // Ah*Bl
                }
#pragma unroll
            for (int mt = 0; mt < 2; mt++)
#pragma unroll
                for (int nt = 0; nt < 4; nt++)
                    mma16816(acc[mt][nt], Al[mt], Bh[nt]);   // Al*Bh
        }
        __syncthreads();
    }

    // ---- epilogue: BN + ReLU + hi/lo split, NHWC packed u32 stores ----
    const float rs = rsqrtf(1.0f + 1e-5f);
    float sc[4][2], bs[4][2];
#pragma unroll
    for (int nt = 0; nt < 4; nt++)
#pragma unroll
        for (int j = 0; j < 2; j++) {
            const int co = z * 64 + warp_n * 32 + nt * 8 + (lane & 3) * 2 + j;
            sc[nt][j] = gma[co] * rs;
            bs[nt][j] = bta[co];
        }

#pragma unroll
    for (int mt = 0; mt < 2; mt++)
#pragma unroll
        for (int ch = 0; ch < 2; ch++) {
            const int p = warp_m * 32 + mt * 16 + (lane >> 2) + ch * 8;
            const size_t base = ((size_t)n * 4096 + r0 * 64 + p) * COUT
                              + z * 64 + warp_n * 32 + (lane & 3) * 2;
#pragma unroll
            for (int nt = 0; nt < 4; nt++) {
                const float v0 = fmaxf(fmaf(acc[mt][nt][ch*2+0], sc[nt][0], bs[nt][0]), 0.f);
                const float v1 = fmaxf(fmaf(acc[mt][nt][ch*2+1], sc[nt][1], bs[nt][1]), 0.f);
                const ushort_t h0 = f2h(v0), h1 = f2h(v1);
                const uint_t ph = (uint_t)h0 | ((uint_t)h1 << 16);
                const uint_t pl = (uint_t)f2h(v0 - h2f(h0))
                                | ((uint_t)f2h(v1 - h2f(h1)) << 16);
                *(uint_t*)(outh + base + nt * 8) = ph;
                *(uint_t*)(outl + base + nt * 8) = pl;
            }
        }
}

// ---------------------------------------------------------------------------
// 1x1 conv head from NHWC bf16 hi/lo; fp32 weights/accum; NCHW fp32 out.
// ---------------------------------------------------------------------------
template <int CI, int CO, bool SOFTPLUS>
__global__ __launch_bounds__(256) void conv1x1_k(
    const ushort_t* __restrict__ inh, const ushort_t* __restrict__ inl,
    const float* __restrict__ w, const float* __restrict__ bias,
    float* __restrict__ out)
{
    __shared__ float s_w[CI * CO];   // [ci][co]
    const int tid = threadIdx.x;
    for (int i = tid; i < CI * CO; i += 256)
        s_w[(i % CI) * CO + i / CI] = w[i];
    __syncthreads();

    const int pid = blockIdx.x * 256 + tid;
    const int n = pid >> 12, p = pid & 4095;
    const ushort_t* ph = inh + (size_t)pid * CI;
    const ushort_t* pl = inl + (size_t)pid * CI;

    float acc[CO];
#pragma unroll
    for (int c = 0; c < CO; c++) acc[c] = 0.f;

#pragma unroll 2
    for (int u = 0; u < CI / 8; u++) {
        const uint4 qh = *(const uint4*)(ph + u * 8);
        const uint4 ql = *(const uint4*)(pl + u * 8);
        const uint_t hw[4] = {qh.x, qh.y, qh.z, qh.w};
        const uint_t lw[4] = {ql.x, ql.y, ql.z, ql.w};
#pragma unroll
        for (int g = 0; g < 4; g++) {
            const float v0 = h2f((ushort_t)hw[g]) + h2f((ushort_t)lw[g]);
            const float v1 = h2f((ushort_t)(hw[g] >> 16)) + h2f((ushort_t)(lw[g] >> 16));
            const int ci = u * 8 + g * 2;
#pragma unroll
            for (int co = 0; co < CO; co++) {
                acc[co] = fmaf(v0, s_w[ci * CO + co], acc[co]);
                acc[co] = fmaf(v1, s_w[(ci + 1) * CO + co], acc[co]);
            }
        }
    }
#pragma unroll
    for (int co = 0; co < CO; co++) {
        float v = acc[co] + bias[co];
        if (SOFTPLUS)
            v = (v > 0.f) ? (v + log1pf(expf(-v))) : log1pf(expf(v));
        out[((size_t)n * CO + co) * NPIX + p] = v;
    }
}

// ---------------------------------------------------------------------------
// Fused postprocessing (unchanged — reads NCHW heat/off)
// ---------------------------------------------------------------------------
__global__ __launch_bounds__(256) void postproc_k(
    const float* __restrict__ heat, const float* __restrict__ off,
    const float* __restrict__ alpha_p, const float* __restrict__ fusion_p,
    float* __restrict__ fw_out, float* __restrict__ coords_out,
    float* __restrict__ scores_out)
{
    __shared__ float r0[256], r1[256], r2[256];
    const int bk  = blockIdx.x;
    const int tid = threadIdx.x;
    const float* hm = heat + (size_t)bk * NPIX;

    float lm = -1e30f;
#pragma unroll
    for (int i = 0; i < 16; i++) lm = fmaxf(lm, hm[tid + i * 256]);
    r0[tid] = lm;
    __syncthreads();
    for (int s = 128; s > 0; s >>= 1) {
        if (tid < s) r0[tid] = fmaxf(r0[tid], r0[tid + s]);
        __syncthreads();
    }
    const float m = r0[0];
    __syncthreads();

    float se = 0.f, sx = 0.f, sy = 0.f;
#pragma unroll
    for (int i = 0; i < 16; i++) {
        const int idx = tid + i * 256;
        const float e = expf(hm[idx] - m);
        se += e;
        sx += e * (float)(idx & 63);
        sy += e * (float)(idx >> 6);
    }
    r0[tid] = se; r1[tid] = sx; r2[tid] = sy;
    __syncthreads();
    for (int s = 128; s > 0; s >>= 1) {
        if (tid < s) {
            r0[tid] += r0[tid + s];
            r1[tid] += r1[tid + s];
            r2[tid] += r2[tid + s];
        }
        __syncthreads();
    }

    if (tid == 0) {
        const float inv = 1.f / r0[0];
        const float xc = r1[0] * inv;
        const float yc = r2[0] * inv;

        const int px = (int)rintf(fminf(fmaxf(xc, 0.f), 63.f));
        const int py = (int)rintf(fminf(fmaxf(yc, 0.f), 63.f));
        int pxs[5], pys[5]; bool okx[5], oky[5];
#pragma unroll
        for (int i = 0; i < 5; i++) {
            const int xs = px - 2 + i; okx[i] = (xs >= 0 && xs < WW); pxs[i] = min(max(xs, 0), 63);
            const int ys = py - 2 + i; oky[i] = (ys >= 0 && ys < HH); pys[i] = min(max(ys, 0), 63);
        }
        float pv[25];
        float pm = -1e30f;
        for (int j = 0; j < 5; j++)
            for (int i = 0; i < 5; i++) {
                const float v = hm[pys[j] * WW + pxs[i]];
                pv[j * 5 + i] = v;
                if (okx[i] && oky[j]) pm = fmaxf(pm, v);
            }
        float ws = 0.f, rx = 0.f, ry = 0.f;
        for (int j = 0; j < 5; j++)
            for (int i = 0; i < 5; i++)
                if (okx[i] && oky[j]) {
                    const float e = expf(pv[j * 5 + i] - pm);
                    ws += e;
                    rx += e * (float)pxs[i];
                    ry += e * (float)pys[j];
                }
        rx /= ws; ry /= ws;

        const float a   = 1.f / (1.f + expf(-alpha_p[0]));
        const float fwv = 1.f / (1.f + expf(-fusion_p[0]));
        float cx = a * xc + (1.f - a) * rx;
        float cy = a * yc + (1.f - a) * ry;

        const float ix = fminf(fmaxf(cx, 0.f), 63.f);
        const float iy = fminf(fmaxf(cy, 0.f), 63.f);
        const float x0f = floorf(ix), y0f = floorf(iy);
        const float wx = ix - x0f, wy = iy - y0f;
        const int x0 = min(max((int)x0f, 0), 63);
        const int y0 = min(max((int)y0f, 0), 63);
        const int x1 = min(x0 + 1, 63);
        const int y1 = min(y0 + 1, 63);
        const float* ob = off + (size_t)bk * 2 * NPIX;
        float sv[2];
#pragma unroll
        for (int ch = 0; ch < 2; ch++) {
            const float* o = ob + ch * NPIX;
            const float v00 = o[y0 * WW + x0], v01 = o[y0 * WW + x1];
            const float v10 = o[y1 * WW + x0], v11 = o[y1 * WW + x1];
            sv[ch] = (1.f - wy) * ((1.f - wx) * v00 + wx * v01)
                   + wy * ((1.f - wx) * v10 + wx * v11);
        }
        cx += fwv * sv[0];
        cy += fwv * sv[1];

        coords_out[bk * 2 + 0] = cx;
        coords_out[bk * 2 + 1] = cy;
        scores_out[bk] = m;
        if (bk == 0) fw_out[0] = fwv;
    }
}

// ---------------------------------------------------------------------------
extern "C" void kernel_launch(void* const* d_in, const int* in_sizes, int n_in,
                              void* d_out, int out_size)
{
    const float* x    = (const float*)d_in[0];
    const float* w_s1 = (const float*)d_in[1];
    const float* g_s1 = (const float*)d_in[2];
    const float* b_s1 = (const float*)d_in[3];
    const float* w_s2 = (const float*)d_in[4];
    const float* g_s2 = (const float*)d_in[5];
    const float* b_s2 = (const float*)d_in[6];
    const float* w_h1 = (const float*)d_in[7];
    const float* g_h1 = (const float*)d_in[8];
    const float* b_h1 = (const float*)d_in[9];
    const float* w_h2 = (const float*)d_in[10];
    const float* c_h2 = (const float*)d_in[11];
    const float* w_o1 = (const float*)d_in[12];
    const float* g_o1 = (const float*)d_in[13];
    const float* b_o1 = (const float*)d_in[14];
    const float* w_o2 = (const float*)d_in[15];
    const float* c_o2 = (const float*)d_in[16];
    const float* w_v1 = (const float*)d_in[17];
    const float* g_v1 = (const float*)d_in[18];
    const float* b_v1 = (const float*)d_in[19];
    const float* w_v2 = (const float*)d_in[20];
    const float* c_v2 = (const float*)d_in[21];
    const float* alpha  = (const float*)d_in[22];
    const float* fusion = (const float*)d_in[23];

    float* out    = (float*)d_out;
    float* heat   = out;
    float* offp   = out + 2228224;
    float* varp   = out + 6684672;
    float* fwp    = out + 8912896;
    float* coords = out + 8912897;
    float* scores = out + 8913985;

    ushort_t *xh, *xl, *ah, *al, *sh, *sl, *th, *tl, *wh, *wl;
    cudaGetSymbolAddress((void**)&xh, g_xh);
    cudaGetSymbolAddress((void**)&xl, g_xl);
    cudaGetSymbolAddress((void**)&ah, g_ah);
    cudaGetSymbolAddress((void**)&al, g_al);
    cudaGetSymbolAddress((void**)&sh, g_sh);
    cudaGetSymbolAddress((void**)&sl, g_sl);
    cudaGetSymbolAddress((void**)&th, g_th);
    cudaGetSymbolAddress((void**)&tl, g_tl);
    cudaGetSymbolAddress((void**)&wh, g_wh);
    cudaGetSymbolAddress((void**)&wl, g_wl);

    const int SMEM = 2 * 49152;   // two 48KB stages
    cudaFuncSetAttribute(conv3x3_mma<256>,
        cudaFuncAttributeMaxDynamicSharedMemorySize, SMEM);
    cudaFuncSetAttribute(conv3x3_mma<128>,
        cudaFuncAttributeMaxDynamicSharedMemorySize, SMEM);

    // weight-prep offsets (elements)
    const size_t O_S1 = 0, O_S2 = 589824, O_H1 = 1179648, O_O1 = 1769472, O_V1 = 2359296;

    dim3 blk(256);
    nchw2nhwc_split<<<dim3(1024, BATCH), blk>>>(x, xh, xl);
    wprep<<<2304, blk>>>(w_s1, wh + O_S1, wl + O_S1, 256);
    wprep<<<2304, blk>>>(w_s2, wh + O_S2, wl + O_S2, 256);
    wprep<<<2304, blk>>>(w_h1, wh + O_H1, wl + O_H1, 256);
    wprep<<<2304, blk>>>(w_o1, wh + O_O1, wl + O_O1, 256);
    wprep<<<1152, blk>>>(w_v1, wh + O_V1, wl + O_V1, 128);

    dim3 g256(32, BATCH, 4);   // Cout=256, N=64 tiles
    dim3 g128(32, BATCH, 2);   // Cout=128

    // stem
    conv3x3_mma<256><<<g256, blk, SMEM>>>(xh, xl, wh + O_S1, wl + O_S1, g_s1, b_s1, ah, al);
    conv3x3_mma<256><<<g256, blk, SMEM>>>(ah, al, wh + O_S2, wl + O_S2, g_s2, b_s2, sh, sl);

    // heatmap head
    conv3x3_mma<256><<<g256, blk, SMEM>>>(sh, sl, wh + O_H1, wl + O_H1, g_h1, b_h1, th, tl);
    conv1x1_k<256, 17, false><<<512, blk>>>(th, tl, w_h2, c_h2, heat);

    // offset head
    conv3x3_mma<256><<<g256, blk, SMEM>>>(sh, sl, wh + O_O1, wl + O_O1, g_o1, b_o1, th, tl);
    conv1x1_k<256, 34, false><<<512, blk>>>(th, tl, w_o2, c_o2, offp);

    // variance head
    conv3x3_mma<128><<<g128, blk, SMEM>>>(sh, sl, wh + O_V1, wl + O_V1, g_v1, b_v1, th, tl);
    conv1x1_k<128, 17, true><<<512, blk>>>(th, tl, w_v2, c_v2, varp);

    // fused soft-argmax + refine + offset sampling
    postproc_k<<<BATCH * KPTS, blk>>>(heat, offp, alpha, fusion, fwp, coords, scores);
}

// round 7
// speedup vs baseline: 1.6793x; 1.6793x over previous
#include <cuda_runtime.h>
#include <cuda_bf16.h>
#include <math.h>

#define CIN   256
#define HH    64
#define WW    64
#define NPIX  4096
#define BATCH 32
#define KPTS  17

typedef unsigned short ushort_t;
typedef unsigned int   uint_t;

// ---------------------------------------------------------------------------
// Scratch (device globals — no runtime allocation allowed)
// Activations NHWC hi/lo: addr = (n*4096 + p)*C + ci
// ---------------------------------------------------------------------------
__device__ __align__(1024) ushort_t g_xh[33554432];
__device__ __align__(1024) ushort_t g_xl[33554432];
__device__ __align__(1024) ushort_t g_ah[33554432];
__device__ __align__(1024) ushort_t g_al[33554432];
__device__ __align__(1024) ushort_t g_sh[33554432];
__device__ __align__(1024) ushort_t g_sl[33554432];
__device__ __align__(1024) ushort_t g_th[33554432];
__device__ __align__(1024) ushort_t g_tl[33554432];
__device__ __align__(1024) ushort_t g_wh[2654208];
__device__ __align__(1024) ushort_t g_wl[2654208];

// ---------------------------------------------------------------------------
__device__ __forceinline__ unsigned smem_to_u32(const void* p) {
    unsigned a;
    asm("{ .reg .u64 t; cvta.to.shared.u64 t, %1; cvt.u32.u64 %0, t; }"
        : "=r"(a) : "l"(p));
    return a;
}
__device__ __forceinline__ ushort_t f2h(float v) {
    __nv_bfloat16 b = __float2bfloat16(v);
    return *(ushort_t*)&b;
}
__device__ __forceinline__ float h2f(ushort_t u) {
    __nv_bfloat16 b = *(__nv_bfloat16*)&u;
    return __bfloat162float(b);
}
__device__ __forceinline__ void ldmatrix_x4(uint_t* r, unsigned addr) {
    asm volatile("ldmatrix.sync.aligned.m8n8.x4.shared.b16 {%0,%1,%2,%3}, [%4];"
                 : "=r"(r[0]), "=r"(r[1]), "=r"(r[2]), "=r"(r[3]) : "r"(addr));
}
__device__ __forceinline__ void mma16816(float* c, const uint_t* a, const uint_t* b) {
    asm volatile(
        "mma.sync.aligned.m16n8k16.row.col.f32.bf16.bf16.f32 "
        "{%0,%1,%2,%3}, {%4,%5,%6,%7}, {%8,%9}, {%0,%1,%2,%3};"
        : "+f"(c[0]), "+f"(c[1]), "+f"(c[2]), "+f"(c[3])
        : "r"(a[0]), "r"(a[1]), "r"(a[2]), "r"(a[3]), "r"(b[0]), "r"(b[1]));
}
__device__ __forceinline__ void cp16(unsigned dst, const void* src, unsigned sz) {
    asm volatile("cp.async.cg.shared.global [%0], [%1], 16, %2;"
                 :: "r"(dst), "l"(src), "r"(sz) : "memory");
}
__device__ __forceinline__ void cp_commit() {
    asm volatile("cp.async.commit_group;" ::: "memory");
}

// ---------------------------------------------------------------------------
// NCHW fp32 -> NHWC bf16 hi/lo split (tiled 32x32 transpose)
// ---------------------------------------------------------------------------
__global__ __launch_bounds__(256) void nchw2nhwc_split(
    const float* __restrict__ x, ushort_t* __restrict__ h,
    ushort_t* __restrict__ l)
{
    __shared__ float t[32][33];
    const int n  = blockIdx.y;
    const int cb = blockIdx.x >> 7;     // 8 ci blocks of 32
    const int pb = blockIdx.x & 127;    // 128 p blocks of 32
    const int lane = threadIdx.x & 31, wr = threadIdx.x >> 5;

    const float* src = x + ((size_t)n * 256 + cb * 32) * 4096 + pb * 32;
#pragma unroll
    for (int j = 0; j < 4; j++) {
        const int ci = wr * 4 + j;
        t[ci][lane] = src[(size_t)ci * 4096 + lane];
    }
    __syncthreads();
#pragma unroll
    for (int j = 0; j < 4; j++) {
        const int p = wr * 4 + j;
        const float v = t[lane][p];
        const ushort_t hb = f2h(v);
        const size_t o = ((size_t)n * 4096 + pb * 32 + p) * 256 + cb * 32 + lane;
        h[o] = hb;
        l[o] = f2h(v - h2f(hb));
    }
}

// ---------------------------------------------------------------------------
// Weight prep: reorder w[co][ci][ky][kx] into 36 chunk-tiles (cc = cb*9 + s),
// each [co][64 ci] K-major with SW128 swizzle baked in, hi/lo split.
// ---------------------------------------------------------------------------
__global__ __launch_bounds__(256) void wprep(
    const float* __restrict__ w, ushort_t* __restrict__ wh,
    ushort_t* __restrict__ wl, int CO)
{
    int idx = blockIdx.x * 256 + threadIdx.x;   // < CO*2304 (exact multiple)
    int co = idx / 2304, r = idx % 2304;
    int ci = r / 9, s = r % 9;
    int cb = ci >> 6, cii = ci & 63;
    int cc = cb * 9 + s;
    unsigned off = (unsigned)(co * 128 + cii * 2) ^ (unsigned)((co & 7) << 4);
    size_t dst = (size_t)cc * CO * 64 + (off >> 1);
    float v = w[idx];
    ushort_t hb = f2h(v);
    wh[dst] = hb;
    wl[dst] = f2h(v - h2f(hb));
}

// ---------------------------------------------------------------------------
// 3x3 SAME conv + BN + ReLU, bf16 hi/lo 3-pass mma.sync, NHWC, cp.async pipe.
// 512 threads (16 warps). COUT=256: M=128px x N=256; COUT=128: M=256px x N=128.
// Double-buffered 96KB stages (192KB smem), 1 CTA/SM.
// ---------------------------------------------------------------------------
template <int COUT>
__global__ __launch_bounds__(512, 1) void conv3x3_mma(
    const ushort_t* __restrict__ inh, const ushort_t* __restrict__ inl,
    const ushort_t* __restrict__ wh,  const ushort_t* __restrict__ wl,
    const float* __restrict__ gma, const float* __restrict__ bta,
    ushort_t* __restrict__ outh, ushort_t* __restrict__ outl)
{
    constexpr int MPIX   = (COUT == 256) ? 128 : 256;
    constexpr int ROWS   = MPIX / 64;
    constexpr int WM     = MPIX / 64;           // warps along M
    constexpr int ABYTES = MPIX * 128;          // per plane
    constexpr int BBYTES = COUT * 128;          // per plane
    constexpr int STAGE  = 2 * ABYTES + 2 * BBYTES;   // 98304

    extern __shared__ __align__(1024) char smem[];
    const unsigned sb = smem_to_u32(smem);
    const int tid = threadIdx.x, wid = tid >> 5, lane = tid & 31;
    const int n = blockIdx.y, r0 = blockIdx.x * ROWS;

    const int warp_m = wid % WM;     // 64 pixels each
    const int warp_n = wid / WM;     // 32 couts each

    float acc[4][4][4];
#pragma unroll
    for (int mt = 0; mt < 4; mt++)
#pragma unroll
        for (int nt = 0; nt < 4; nt++)
#pragma unroll
            for (int c = 0; c < 4; c++) acc[mt][nt][c] = 0.f;

    // -------- async stage fill --------
    auto issue = [&](int cc, int st) {
        const int cb = cc / 9, s = cc - cb * 9;
        const int ky = s / 3, kx = s - ky * 3;
        const unsigned sbase = sb + st * STAGE;
        // A tiles (hi+lo): MPIX*16 chunks of 16B
#pragma unroll
        for (int i = tid; i < MPIX * 16; i += 512) {
            const int plane = i / (MPIX * 8);
            const int r = i - plane * (MPIX * 8);
            const int px = r >> 3, g = r & 7;
            const int row = r0 + (px >> 6) + ky - 1;
            const int col = (px & 63) + kx - 1;
            const bool ok = (row >= 0) && (row < HH) && (col >= 0) && (col < WW);
            const ushort_t* src = (plane ? inl : inh)
                + ((size_t)(n * 4096 + (ok ? row * 64 + col : 0))) * 256
                + cb * 64 + g * 8;
            const unsigned dst = sbase + plane * ABYTES
                + (((unsigned)(px * 128 + g * 16)) ^ ((unsigned)((px & 7) << 4)));
            cp16(dst, src, ok ? 16u : 0u);
        }
        // B tiles (hi+lo): COUT*16 chunks of 16B, pre-swizzled contiguous
#pragma unroll
        for (int i = tid; i < COUT * 16; i += 512) {
            const int plane = i / (COUT * 8);
            const int r = i - plane * (COUT * 8);
            const ushort_t* src = (plane ? wl : wh) + (size_t)cc * COUT * 64 + r * 8;
            const unsigned dst = sbase + 2 * ABYTES + plane * BBYTES + r * 16;
            cp16(dst, src, 16);
        }
        cp_commit();
    };

    issue(0, 0);

    for (int cc = 0; cc < 36; cc++) {
        const int cur = cc & 1;
        if (cc < 35) {
            issue(cc + 1, cur ^ 1);
            asm volatile("cp.async.wait_group 1;" ::: "memory");
        } else {
            asm volatile("cp.async.wait_group 0;" ::: "memory");
        }
        __syncthreads();

        const unsigned ab = sb + cur * STAGE;
        const unsigned bb = ab + 2 * ABYTES;
#pragma unroll
        for (int k4 = 0; k4 < 4; k4++) {
            const unsigned kb = (unsigned)(k4 * 32);
            uint_t Bh[4][2], Bl[4][2];
            {   // ldmatrix.x4 covers 2 nt tiles per call
                const int j = lane & 7, g = lane >> 3;
                const int ntp = g >> 1, kh = g & 1;
#pragma unroll
                for (int q = 0; q < 2; q++) {
                    const unsigned row = (unsigned)(warp_n * 32 + (q * 2 + ntp) * 8 + j);
                    const unsigned off = (row * 128 + kb + (unsigned)(kh * 16))
                                         ^ ((unsigned)j << 4);
                    uint_t r[4];
                    ldmatrix_x4(r, bb + off);
                    Bh[q*2][0] = r[0]; Bh[q*2][1] = r[1];
                    Bh[q*2+1][0] = r[2]; Bh[q*2+1][1] = r[3];
                    ldmatrix_x4(r, bb + BBYTES + off);
                    Bl[q*2][0] = r[0]; Bl[q*2][1] = r[1];
                    Bl[q*2+1][0] = r[2]; Bl[q*2+1][1] = r[3];
                }
            }
#pragma unroll
            for (int mt = 0; mt < 4; mt++) {
                const unsigned arow = (unsigned)(warp_m * 64 + mt * 16 + (lane & 15));
                const unsigned off = (arow * 128 + kb + (unsigned)((lane >> 4) << 4))
                                     ^ ((arow & 7) << 4);
                uint_t A[4];
                ldmatrix_x4(A, ab + off);                 // Ah
#pragma unroll
                for (int nt = 0; nt < 4; nt++) {
                    mma16816(acc[mt][nt], A, Bh[nt]);     // Ah*Bh
                    mma16816(acc[mt][nt], A, Bl[nt]);     // Ah*Bl
                }
            }
#pragma unroll
            for (int mt = 0; mt < 4; mt++) {
                const unsigned arow = (unsigned)(warp_m * 64 + mt * 16 + (lane & 15));
                const unsigned off = (arow * 128 + kb + (unsigned)((lane >> 4) << 4))
                                     ^ ((arow & 7) << 4);
                uint_t A[4];
                ldmatrix_x4(A, ab + ABYTES + off);        // Al
#pragma unroll
                for (int nt = 0; nt < 4; nt++)
                    mma16816(acc[mt][nt], A, Bh[nt]);     // Al*Bh
            }
        }
        __syncthreads();
    }

    // ---- epilogue: BN + ReLU + hi/lo split, NHWC packed u32 stores ----
    const float rs = rsqrtf(1.0f + 1e-5f);
    float sc[4][2], bs[4][2];
#pragma unroll
    for (int nt = 0; nt < 4; nt++)
#pragma unroll
        for (int j = 0; j < 2; j++) {
            const int co = warp_n * 32 + nt * 8 + (lane & 3) * 2 + j;
            sc[nt][j] = gma[co] * rs;
            bs[nt][j] = bta[co];
        }

#pragma unroll
    for (int mt = 0; mt < 4; mt++)
#pragma unroll
        for (int ch = 0; ch < 2; ch++) {
            const int p = warp_m * 64 + mt * 16 + (lane >> 2) + ch * 8;
            const size_t base = ((size_t)n * 4096 + r0 * 64 + p) * COUT
                              + warp_n * 32 + (lane & 3) * 2;
#pragma unroll
            for (int nt = 0; nt < 4; nt++) {
                const float v0 = fmaxf(fmaf(acc[mt][nt][ch*2+0], sc[nt][0], bs[nt][0]), 0.f);
                const float v1 = fmaxf(fmaf(acc[mt][nt][ch*2+1], sc[nt][1], bs[nt][1]), 0.f);
                const ushort_t h0 = f2h(v0), h1 = f2h(v1);
                const uint_t ph = (uint_t)h0 | ((uint_t)h1 << 16);
                const uint_t pl = (uint_t)f2h(v0 - h2f(h0))
                                | ((uint_t)f2h(v1 - h2f(h1)) << 16);
                *(uint_t*)(outh + base + nt * 8) = ph;
                *(uint_t*)(outl + base + nt * 8) = pl;
            }
        }
}

// ---------------------------------------------------------------------------
// 1x1 conv head from NHWC bf16 hi/lo; fp32 weights/accum; NCHW fp32 out.
// ---------------------------------------------------------------------------
template <int CI, int CO, bool SOFTPLUS>
__global__ __launch_bounds__(256) void conv1x1_k(
    const ushort_t* __restrict__ inh, const ushort_t* __restrict__ inl,
    const float* __restrict__ w, const float* __restrict__ bias,
    float* __restrict__ out)
{
    __shared__ float s_w[CI * CO];   // [ci][co]
    const int tid = threadIdx.x;
    for (int i = tid; i < CI * CO; i += 256)
        s_w[(i % CI) * CO + i / CI] = w[i];
    __syncthreads();

    const int pid = blockIdx.x * 256 + tid;
    const int n = pid >> 12, p = pid & 4095;
    const ushort_t* ph = inh + (size_t)pid * CI;
    const ushort_t* pl = inl + (size_t)pid * CI;

    float acc[CO];
#pragma unroll
    for (int c = 0; c < CO; c++) acc[c] = 0.f;

#pragma unroll 2
    for (int u = 0; u < CI / 8; u++) {
        const uint4 qh = *(const uint4*)(ph + u * 8);
        const uint4 ql = *(const uint4*)(pl + u * 8);
        const uint_t hw[4] = {qh.x, qh.y, qh.z, qh.w};
        const uint_t lw[4] = {ql.x, ql.y, ql.z, ql.w};
#pragma unroll
        for (int g = 0; g < 4; g++) {
            const float v0 = h2f((ushort_t)hw[g]) + h2f((ushort_t)lw[g]);
            const float v1 = h2f((ushort_t)(hw[g] >> 16)) + h2f((ushort_t)(lw[g] >> 16));
            const int ci = u * 8 + g * 2;
#pragma unroll
            for (int co = 0; co < CO; co++) {
                acc[co] = fmaf(v0, s_w[ci * CO + co], acc[co]);
                acc[co] = fmaf(v1, s_w[(ci + 1) * CO + co], acc[co]);
            }
        }
    }
#pragma unroll
    for (int co = 0; co < CO; co++) {
        float v = acc[co] + bias[co];
        if (SOFTPLUS)
            v = (v > 0.f) ? (v + log1pf(expf(-v))) : log1pf(expf(v));
        out[((size_t)n * CO + co) * NPIX + p] = v;
    }
}

// ---------------------------------------------------------------------------
// Fused postprocessing (reads NCHW heat/off)
// ---------------------------------------------------------------------------
__global__ __launch_bounds__(256) void postproc_k(
    const float* __restrict__ heat, const float* __restrict__ off,
    const float* __restrict__ alpha_p, const float* __restrict__ fusion_p,
    float* __restrict__ fw_out, float* __restrict__ coords_out,
    float* __restrict__ scores_out)
{
    __shared__ float r0[256], r1[256], r2[256];
    const int bk  = blockIdx.x;
    const int tid = threadIdx.x;
    const float* hm = heat + (size_t)bk * NPIX;

    float lm = -1e30f;
#pragma unroll
    for (int i = 0; i < 16; i++) lm = fmaxf(lm, hm[tid + i * 256]);
    r0[tid] = lm;
    __syncthreads();
    for (int s = 128; s > 0; s >>= 1) {
        if (tid < s) r0[tid] = fmaxf(r0[tid], r0[tid + s]);
        __syncthreads();
    }
    const float m = r0[0];
    __syncthreads();

    float se = 0.f, sx = 0.f, sy = 0.f;
#pragma unroll
    for (int i = 0; i < 16; i++) {
        const int idx = tid + i * 256;
        const float e = expf(hm[idx] - m);
        se += e;
        sx += e * (float)(idx & 63);
        sy += e * (float)(idx >> 6);
    }
    r0[tid] = se; r1[tid] = sx; r2[tid] = sy;
    __syncthreads();
    for (int s = 128; s > 0; s >>= 1) {
        if (tid < s) {
            r0[tid] += r0[tid + s];
            r1[tid] += r1[tid + s];
            r2[tid] += r2[tid + s];
        }
        __syncthreads();
    }

    if (tid == 0) {
        const float inv = 1.f / r0[0];
        const float xc = r1[0] * inv;
        const float yc = r2[0] * inv;

        const int px = (int)rintf(fminf(fmaxf(xc, 0.f), 63.f));
        const int py = (int)rintf(fminf(fmaxf(yc, 0.f), 63.f));
        int pxs[5], pys[5]; bool okx[5], oky[5];
#pragma unroll
        for (int i = 0; i < 5; i++) {
            const int xs = px - 2 + i; okx[i] = (xs >= 0 && xs < WW); pxs[i] = min(max(xs, 0), 63);
            const int ys = py - 2 + i; oky[i] = (ys >= 0 && ys < HH); pys[i] = min(max(ys, 0), 63);
        }
        float pv[25];
        float pm = -1e30f;
        for (int j = 0; j < 5; j++)
            for (int i = 0; i < 5; i++) {
                const float v = hm[pys[j] * WW + pxs[i]];
                pv[j * 5 + i] = v;
                if (okx[i] && oky[j]) pm = fmaxf(pm, v);
            }
        float ws = 0.f, rx = 0.f, ry = 0.f;
        for (int j = 0; j < 5; j++)
            for (int i = 0; i < 5; i++)
                if (okx[i] && oky[j]) {
                    const float e = expf(pv[j * 5 + i] - pm);
                    ws += e;
                    rx += e * (float)pxs[i];
                    ry += e * (float)pys[j];
                }
        rx /= ws; ry /= ws;

        const float a   = 1.f / (1.f + expf(-alpha_p[0]));
        const float fwv = 1.f / (1.f + expf(-fusion_p[0]));
        float cx = a * xc + (1.f - a) * rx;
        float cy = a * yc + (1.f - a) * ry;

        const float ix = fminf(fmaxf(cx, 0.f), 63.f);
        const float iy = fminf(fmaxf(cy, 0.f), 63.f);
        const float x0f = floorf(ix), y0f = floorf(iy);
        const float wx = ix - x0f, wy = iy - y0f;
        const int x0 = min(max((int)x0f, 0), 63);
        const int y0 = min(max((int)y0f, 0), 63);
        const int x1 = min(x0 + 1, 63);
        const int y1 = min(y0 + 1, 63);
        const float* ob = off + (size_t)bk * 2 * NPIX;
        float sv[2];
#pragma unroll
        for (int ch = 0; ch < 2; ch++) {
            const float* o = ob + ch * NPIX;
            const float v00 = o[y0 * WW + x0], v01 = o[y0 * WW + x1];
            const float v10 = o[y1 * WW + x0], v11 = o[y1 * WW + x1];
            sv[ch] = (1.f - wy) * ((1.f - wx) * v00 + wx * v01)
                   + wy * ((1.f - wx) * v10 + wx * v11);
        }
        cx += fwv * sv[0];
        cy += fwv * sv[1];

        coords_out[bk * 2 + 0] = cx;
        coords_out[bk * 2 + 1] = cy;
        scores_out[bk] = m;
        if (bk == 0) fw_out[0] = fwv;
    }
}

// ---------------------------------------------------------------------------
extern "C" void kernel_launch(void* const* d_in, const int* in_sizes, int n_in,
                              void* d_out, int out_size)
{
    const float* x    = (const float*)d_in[0];
    const float* w_s1 = (const float*)d_in[1];
    const float* g_s1 = (const float*)d_in[2];
    const float* b_s1 = (const float*)d_in[3];
    const float* w_s2 = (const float*)d_in[4];
    const float* g_s2 = (const float*)d_in[5];
    const float* b_s2 = (const float*)d_in[6];
    const float* w_h1 = (const float*)d_in[7];
    const float* g_h1 = (const float*)d_in[8];
    const float* b_h1 = (const float*)d_in[9];
    const float* w_h2 = (const float*)d_in[10];
    const float* c_h2 = (const float*)d_in[11];
    const float* w_o1 = (const float*)d_in[12];
    const float* g_o1 = (const float*)d_in[13];
    const float* b_o1 = (const float*)d_in[14];
    const float* w_o2 = (const float*)d_in[15];
    const float* c_o2 = (const float*)d_in[16];
    const float* w_v1 = (const float*)d_in[17];
    const float* g_v1 = (const float*)d_in[18];
    const float* b_v1 = (const float*)d_in[19];
    const float* w_v2 = (const float*)d_in[20];
    const float* c_v2 = (const float*)d_in[21];
    const float* alpha  = (const float*)d_in[22];
    const float* fusion = (const float*)d_in[23];

    float* out    = (float*)d_out;
    float* heat   = out;
    float* offp   = out + 2228224;
    float* varp   = out + 6684672;
    float* fwp    = out + 8912896;
    float* coords = out + 8912897;
    float* scores = out + 8913985;

    ushort_t *xh, *xl, *ah, *al, *sh, *sl, *th, *tl, *wh, *wl;
    cudaGetSymbolAddress((void**)&xh, g_xh);
    cudaGetSymbolAddress((void**)&xl, g_xl);
    cudaGetSymbolAddress((void**)&ah, g_ah);
    cudaGetSymbolAddress((void**)&al, g_al);
    cudaGetSymbolAddress((void**)&sh, g_sh);
    cudaGetSymbolAddress((void**)&sl, g_sl);
    cudaGetSymbolAddress((void**)&th, g_th);
    cudaGetSymbolAddress((void**)&tl, g_tl);
    cudaGetSymbolAddress((void**)&wh, g_wh);
    cudaGetSymbolAddress((void**)&wl, g_wl);

    const int SMEM = 2 * 98304;   // two 96KB stages
    cudaFuncSetAttribute(conv3x3_mma<256>,
        cudaFuncAttributeMaxDynamicSharedMemorySize, SMEM);
    cudaFuncSetAttribute(conv3x3_mma<128>,
        cudaFuncAttributeMaxDynamicSharedMemorySize, SMEM);

    // weight-prep offsets (elements)
    const size_t O_S1 = 0, O_S2 = 589824, O_H1 = 1179648, O_O1 = 1769472, O_V1 = 2359296;

    dim3 blk(256);
    nchw2nhwc_split<<<dim3(1024, BATCH), blk>>>(x, xh, xl);
    wprep<<<2304, blk>>>(w_s1, wh + O_S1, wl + O_S1, 256);
    wprep<<<2304, blk>>>(w_s2, wh + O_S2, wl + O_S2, 256);
    wprep<<<2304, blk>>>(w_h1, wh + O_H1, wl + O_H1, 256);
    wprep<<<2304, blk>>>(w_o1, wh + O_O1, wl + O_O1, 256);
    wprep<<<1152, blk>>>(w_v1, wh + O_V1, wl + O_V1, 128);

    dim3 cblk(512);
    dim3 g256(32, BATCH);   // M=128 pixel tiles (2 rows)
    dim3 g128(16, BATCH);   // M=256 pixel tiles (4 rows)

    // stem
    conv3x3_mma<256><<<g256, cblk, SMEM>>>(xh, xl, wh + O_S1, wl + O_S1, g_s1, b_s1, ah, al);
    conv3x3_mma<256><<<g256, cblk, SMEM>>>(ah, al, wh + O_S2, wl + O_S2, g_s2, b_s2, sh, sl);

    // heatmap head
    conv3x3_mma<256><<<g256, cblk, SMEM>>>(sh, sl, wh + O_H1, wl + O_H1, g_h1, b_h1, th, tl);
    conv1x1_k<256, 17, false><<<512, blk>>>(th, tl, w_h2, c_h2, heat);

    // offset head
    conv3x3_mma<256><<<g256, cblk, SMEM>>>(sh, sl, wh + O_O1, wl + O_O1, g_o1, b_o1, th, tl);
    conv1x1_k<256, 34, false><<<512, blk>>>(th, tl, w_o2, c_o2, offp);

    // variance head
    conv3x3_mma<128><<<g128, cblk, SMEM>>>(sh, sl, wh + O_V1, wl + O_V1, g_v1, b_v1, th, tl);
    conv1x1_k<128, 17, true><<<512, blk>>>(th, tl, w_v2, c_v2, varp);

    // fused soft-argmax + refine + offset sampling
    postproc_k<<<BATCH * KPTS, blk>>>(heat, offp, alpha, fusion, fwp, coords, scores);
}

// round 8
// speedup vs baseline: 2.0306x; 1.2091x over previous
#include <cuda_runtime.h>
#include <cuda_fp16.h>
#include <math.h>

#define CIN   256
#define HH    64
#define WW    64
#define NPIX  4096
#define BATCH 32
#define KPTS  17

typedef unsigned short ushort_t;
typedef unsigned int   uint_t;

// ---------------------------------------------------------------------------
// Scratch (device globals — no runtime allocation allowed)
// Activations NHWC fp16 hi/lo: addr = (n*4096 + p)*C + ci
// ---------------------------------------------------------------------------
__device__ __align__(1024) ushort_t g_xh[33554432];
__device__ __align__(1024) ushort_t g_xl[33554432];
__device__ __align__(1024) ushort_t g_ah[33554432];
__device__ __align__(1024) ushort_t g_al[33554432];
__device__ __align__(1024) ushort_t g_sh[33554432];
__device__ __align__(1024) ushort_t g_sl[33554432];
__device__ __align__(1024) ushort_t g_th[33554432];
__device__ __align__(1024) ushort_t g_tl[33554432];
__device__ __align__(1024) ushort_t g_wh[2654208];
__device__ __align__(1024) ushort_t g_wl[2654208];

// ---------------------------------------------------------------------------
__device__ __forceinline__ unsigned smem_to_u32(const void* p) {
    unsigned a;
    asm("{ .reg .u64 t; cvta.to.shared.u64 t, %1; cvt.u32.u64 %0, t; }"
        : "=r"(a) : "l"(p));
    return a;
}
__device__ __forceinline__ ushort_t f2h(float v) {
    __half h = __float2half_rn(v);
    return *(ushort_t*)&h;
}
__device__ __forceinline__ float h2f(ushort_t u) {
    __half h = *(__half*)&u;
    return __half2float(h);
}
__device__ __forceinline__ void ldmatrix_x4(uint_t* r, unsigned addr) {
    asm volatile("ldmatrix.sync.aligned.m8n8.x4.shared.b16 {%0,%1,%2,%3}, [%4];"
                 : "=r"(r[0]), "=r"(r[1]), "=r"(r[2]), "=r"(r[3]) : "r"(addr));
}
__device__ __forceinline__ void mma16816(float* c, const uint_t* a, const uint_t* b) {
    asm volatile(
        "mma.sync.aligned.m16n8k16.row.col.f32.f16.f16.f32 "
        "{%0,%1,%2,%3}, {%4,%5,%6,%7}, {%8,%9}, {%0,%1,%2,%3};"
        : "+f"(c[0]), "+f"(c[1]), "+f"(c[2]), "+f"(c[3])
        : "r"(a[0]), "r"(a[1]), "r"(a[2]), "r"(a[3]), "r"(b[0]), "r"(b[1]));
}
__device__ __forceinline__ void cp16(unsigned dst, const void* src, unsigned sz) {
    asm volatile("cp.async.cg.shared.global [%0], [%1], 16, %2;"
                 :: "r"(dst), "l"(src), "r"(sz) : "memory");
}
__device__ __forceinline__ void cp_commit() {
    asm volatile("cp.async.commit_group;" ::: "memory");
}

// ---------------------------------------------------------------------------
// NCHW fp32 -> NHWC fp16 hi/lo split (tiled 32x32 transpose)
// ---------------------------------------------------------------------------
__global__ __launch_bounds__(256) void nchw2nhwc_split(
    const float* __restrict__ x, ushort_t* __restrict__ h,
    ushort_t* __restrict__ l)
{
    __shared__ float t[32][33];
    const int n  = blockIdx.y;
    const int cb = blockIdx.x >> 7;
    const int pb = blockIdx.x & 127;
    const int lane = threadIdx.x & 31, wr = threadIdx.x >> 5;

    const float* src = x + ((size_t)n * 256 + cb * 32) * 4096 + pb * 32;
#pragma unroll
    for (int j = 0; j < 4; j++) {
        const int ci = wr * 4 + j;
        t[ci][lane] = src[(size_t)ci * 4096 + lane];
    }
    __syncthreads();
#pragma unroll
    for (int j = 0; j < 4; j++) {
        const int p = wr * 4 + j;
        const float v = t[lane][p];
        const ushort_t hb = f2h(v);
        const size_t o = ((size_t)n * 4096 + pb * 32 + p) * 256 + cb * 32 + lane;
        h[o] = hb;
        l[o] = f2h(v - h2f(hb));
    }
}

// ---------------------------------------------------------------------------
// Weight prep: reorder w[co][ci][ky][kx] into 36 chunk-tiles (cc = cb*9 + s),
// each [co][64 ci] K-major with SW128 swizzle baked in, fp16 hi/lo split.
// ---------------------------------------------------------------------------
__global__ __launch_bounds__(256) void wprep(
    const float* __restrict__ w, ushort_t* __restrict__ wh,
    ushort_t* __restrict__ wl, int CO)
{
    int idx = blockIdx.x * 256 + threadIdx.x;
    int co = idx / 2304, r = idx % 2304;
    int ci = r / 9, s = r % 9;
    int cb = ci >> 6, cii = ci & 63;
    int cc = cb * 9 + s;
    unsigned off = (unsigned)(co * 128 + cii * 2) ^ (unsigned)((co & 7) << 4);
    size_t dst = (size_t)cc * CO * 64 + (off >> 1);
    float v = w[idx];
    ushort_t hb = f2h(v);
    wh[dst] = hb;
    wl[dst] = f2h(v - h2f(hb));
}

// ---------------------------------------------------------------------------
// 3x3 SAME conv + BN + ReLU, fp16 hi/lo split mma.sync, NHWC, cp.async pipe.
// PASSES=3: AhBh + AhBl + AlBh (err ~2^-22). PASSES=2: AhBh + AlBh (err ~2^-11).
// 512 threads. COUT=256: M=128px x N=256; COUT=128: M=256px x N=128.
// ---------------------------------------------------------------------------
template <int COUT, int PASSES>
__global__ __launch_bounds__(512, 1) void conv3x3_mma(
    const ushort_t* __restrict__ inh, const ushort_t* __restrict__ inl,
    const ushort_t* __restrict__ wh,  const ushort_t* __restrict__ wl,
    const float* __restrict__ gma, const float* __restrict__ bta,
    ushort_t* __restrict__ outh, ushort_t* __restrict__ outl)
{
    constexpr int MPIX   = (COUT == 256) ? 128 : 256;
    constexpr int ROWS   = MPIX / 64;
    constexpr int WM     = MPIX / 64;
    constexpr int ABYTES = MPIX * 128;
    constexpr int BBYTES = COUT * 128;
    constexpr int STAGE  = 2 * ABYTES + 2 * BBYTES;
    constexpr int BPL    = (PASSES == 3) ? 2 : 1;

    extern __shared__ __align__(1024) char smem[];
    const unsigned sb = smem_to_u32(smem);
    const int tid = threadIdx.x, wid = tid >> 5, lane = tid & 31;
    const int n = blockIdx.y, r0 = blockIdx.x * ROWS;

    const int warp_m = wid % WM;
    const int warp_n = wid / WM;

    float acc[4][4][4];
#pragma unroll
    for (int mt = 0; mt < 4; mt++)
#pragma unroll
        for (int nt = 0; nt < 4; nt++)
#pragma unroll
            for (int c = 0; c < 4; c++) acc[mt][nt][c] = 0.f;

    auto issue = [&](int cc, int st) {
        const int cb = cc / 9, s = cc - cb * 9;
        const int ky = s / 3, kx = s - ky * 3;
        const unsigned sbase = sb + st * STAGE;
#pragma unroll
        for (int i = tid; i < MPIX * 16; i += 512) {
            const int plane = i / (MPIX * 8);
            const int r = i - plane * (MPIX * 8);
            const int px = r >> 3, g = r & 7;
            const int row = r0 + (px >> 6) + ky - 1;
            const int col = (px & 63) + kx - 1;
            const bool ok = (row >= 0) && (row < HH) && (col >= 0) && (col < WW);
            const ushort_t* src = (plane ? inl : inh)
                + ((size_t)(n * 4096 + (ok ? row * 64 + col : 0))) * 256
                + cb * 64 + g * 8;
            const unsigned dst = sbase + plane * ABYTES
                + (((unsigned)(px * 128 + g * 16)) ^ ((unsigned)((px & 7) << 4)));
            cp16(dst, src, ok ? 16u : 0u);
        }
#pragma unroll
        for (int i = tid; i < COUT * 8 * BPL; i += 512) {
            const int plane = i / (COUT * 8);
            const int r = i - plane * (COUT * 8);
            const ushort_t* src = (plane ? wl : wh) + (size_t)cc * COUT * 64 + r * 8;
            const unsigned dst = sbase + 2 * ABYTES + plane * BBYTES + r * 16;
            cp16(dst, src, 16);
        }
        cp_commit();
    };

    issue(0, 0);

    for (int cc = 0; cc < 36; cc++) {
        const int cur = cc & 1;
        if (cc < 35) {
            issue(cc + 1, cur ^ 1);
            asm volatile("cp.async.wait_group 1;" ::: "memory");
        } else {
            asm volatile("cp.async.wait_group 0;" ::: "memory");
        }
        __syncthreads();

        const unsigned ab = sb + cur * STAGE;
        const unsigned bb = ab + 2 * ABYTES;
#pragma unroll
        for (int k4 = 0; k4 < 4; k4++) {
            const unsigned kb = (unsigned)(k4 * 32);
            uint_t Bh[4][2], Bl[4][2];
            {
                const int j = lane & 7, g = lane >> 3;
                const int ntp = g >> 1, kh = g & 1;
#pragma unroll
                for (int q = 0; q < 2; q++) {
                    const unsigned row = (unsigned)(warp_n * 32 + (q * 2 + ntp) * 8 + j);
                    const unsigned off = (row * 128 + kb + (unsigned)(kh * 16))
                                         ^ ((unsigned)j << 4);
                    uint_t r[4];
                    ldmatrix_x4(r, bb + off);
                    Bh[q*2][0] = r[0]; Bh[q*2][1] = r[1];
                    Bh[q*2+1][0] = r[2]; Bh[q*2+1][1] = r[3];
                    if (PASSES == 3) {
                        ldmatrix_x4(r, bb + BBYTES + off);
                        Bl[q*2][0] = r[0]; Bl[q*2][1] = r[1];
                        Bl[q*2+1][0] = r[2]; Bl[q*2+1][1] = r[3];
                    }
                }
            }
#pragma unroll
            for (int mt = 0; mt < 4; mt++) {
                const unsigned arow = (unsigned)(warp_m * 64 + mt * 16 + (lane & 15));
                const unsigned off = (arow * 128 + kb + (unsigned)((lane >> 4) << 4))
                                     ^ ((arow & 7) << 4);
                uint_t A[4];
                ldmatrix_x4(A, ab + off);                 // Ah
#pragma unroll
                for (int nt = 0; nt < 4; nt++) {
                    mma16816(acc[mt][nt], A, Bh[nt]);     // Ah*Bh
                    if (PASSES == 3)
                        mma16816(acc[mt][nt], A, Bl[nt]); // Ah*Bl
                }
            }
#pragma unroll
            for (int mt = 0; mt < 4; mt++) {
                const unsigned arow = (unsigned)(warp_m * 64 + mt * 16 + (lane & 15));
                const unsigned off = (arow * 128 + kb + (unsigned)((lane >> 4) << 4))
                                     ^ ((arow & 7) << 4);
                uint_t A[4];
                ldmatrix_x4(A, ab + ABYTES + off);        // Al
#pragma unroll
                for (int nt = 0; nt < 4; nt++)
                    mma16816(acc[mt][nt], A, Bh[nt]);     // Al*Bh
            }
        }
        __syncthreads();
    }

    // ---- epilogue: BN + ReLU + fp16 hi/lo split, NHWC packed u32 stores ----
    const float rs = rsqrtf(1.0f + 1e-5f);
    float sc[4][2], bs[4][2];
#pragma unroll
    for (int nt = 0; nt < 4; nt++)
#pragma unroll
        for (int j = 0; j < 2; j++) {
            const int co = warp_n * 32 + nt * 8 + (lane & 3) * 2 + j;
            sc[nt][j] = gma[co] * rs;
            bs[nt][j] = bta[co];
        }

#pragma unroll
    for (int mt = 0; mt < 4; mt++)
#pragma unroll
        for (int ch = 0; ch < 2; ch++) {
            const int p = warp_m * 64 + mt * 16 + (lane >> 2) + ch * 8;
            const size_t base = ((size_t)n * 4096 + r0 * 64 + p) * COUT
                              + warp_n * 32 + (lane & 3) * 2;
#pragma unroll
            for (int nt = 0; nt < 4; nt++) {
                const float v0 = fmaxf(fmaf(acc[mt][nt][ch*2+0], sc[nt][0], bs[nt][0]), 0.f);
                const float v1 = fmaxf(fmaf(acc[mt][nt][ch*2+1], sc[nt][1], bs[nt][1]), 0.f);
                const ushort_t h0 = f2h(v0), h1 = f2h(v1);
                const uint_t ph = (uint_t)h0 | ((uint_t)h1 << 16);
                const uint_t pl = (uint_t)f2h(v0 - h2f(h0))
                                | ((uint_t)f2h(v1 - h2f(h1)) << 16);
                *(uint_t*)(outh + base + nt * 8) = ph;
                *(uint_t*)(outl + base + nt * 8) = pl;
            }
        }
}

// ---------------------------------------------------------------------------
// 1x1 conv head from NHWC fp16 hi/lo; fp32 weights/accum; NCHW fp32 out.
// PPT pixels per thread: each broadcast-LDS weight feeds PPT FMAs.
// ---------------------------------------------------------------------------
template <int CI, int CO, int PPT, bool SOFTPLUS>
__global__ __launch_bounds__(256) void conv1x1_k(
    const ushort_t* __restrict__ inh, const ushort_t* __restrict__ inl,
    const float* __restrict__ w, const float* __restrict__ bias,
    float* __restrict__ out)
{
    __shared__ float s_w[CI * CO];   // [ci][co]
    const int tid = threadIdx.x;
    for (int i = tid; i < CI * CO; i += 256)
        s_w[(i % CI) * CO + i / CI] = w[i];
    __syncthreads();

    const int pid0 = (blockIdx.x * 256 + tid) * PPT;
    const int n = pid0 >> 12;

    float acc[PPT][CO];
#pragma unroll
    for (int q = 0; q < PPT; q++)
#pragma unroll
        for (int c = 0; c < CO; c++) acc[q][c] = 0.f;

    for (int u = 0; u < CI / 8; u++) {
        float v[PPT][8];
#pragma unroll
        for (int q = 0; q < PPT; q++) {
            const uint4 qh = *(const uint4*)(inh + (size_t)(pid0 + q) * CI + u * 8);
            const uint4 ql = *(const uint4*)(inl + (size_t)(pid0 + q) * CI + u * 8);
            const uint_t hw[4] = {qh.x, qh.y, qh.z, qh.w};
            const uint_t lw[4] = {ql.x, ql.y, ql.z, ql.w};
#pragma unroll
            for (int g = 0; g < 4; g++) {
                v[q][g*2+0] = h2f((ushort_t)hw[g]) + h2f((ushort_t)lw[g]);
                v[q][g*2+1] = h2f((ushort_t)(hw[g] >> 16)) + h2f((ushort_t)(lw[g] >> 16));
            }
        }
#pragma unroll
        for (int g = 0; g < 8; g++) {
            const int ci = u * 8 + g;
#pragma unroll
            for (int co = 0; co < CO; co++) {
                const float wv = s_w[ci * CO + co];
#pragma unroll
                for (int q = 0; q < PPT; q++)
                    acc[q][co] = fmaf(v[q][g], wv, acc[q][co]);
            }
        }
    }
#pragma unroll
    for (int q = 0; q < PPT; q++) {
        const int p = (pid0 + q) & 4095;
#pragma unroll
        for (int co = 0; co < CO; co++) {
            float o = acc[q][co] + bias[co];
            if (SOFTPLUS)
                o = (o > 0.f) ? (o + log1pf(expf(-o))) : log1pf(expf(o));
            out[((size_t)n * CO + co) * NPIX + p] = o;
        }
    }
}

// ---------------------------------------------------------------------------
// Fused postprocessing (reads NCHW heat/off)
// ---------------------------------------------------------------------------
__global__ __launch_bounds__(256) void postproc_k(
    const float* __restrict__ heat, const float* __restrict__ off,
    const float* __restrict__ alpha_p, const float* __restrict__ fusion_p,
    float* __restrict__ fw_out, float* __restrict__ coords_out,
    float* __restrict__ scores_out)
{
    __shared__ float r0[256], r1[256], r2[256];
    const int bk  = blockIdx.x;
    const int tid = threadIdx.x;
    const float* hm = heat + (size_t)bk * NPIX;

    float lm = -1e30f;
#pragma unroll
    for (int i = 0; i < 16; i++) lm = fmaxf(lm, hm[tid + i * 256]);
    r0[tid] = lm;
    __syncthreads();
    for (int s = 128; s > 0; s >>= 1) {
        if (tid < s) r0[tid] = fmaxf(r0[tid], r0[tid + s]);
        __syncthreads();
    }
    const float m = r0[0];
    __syncthreads();

    float se = 0.f, sx = 0.f, sy = 0.f;
#pragma unroll
    for (int i = 0; i < 16; i++) {
        const int idx = tid + i * 256;
        const float e = expf(hm[idx] - m);
        se += e;
        sx += e * (float)(idx & 63);
        sy += e * (float)(idx >> 6);
    }
    r0[tid] = se; r1[tid] = sx; r2[tid] = sy;
    __syncthreads();
    for (int s = 128; s > 0; s >>= 1) {
        if (tid < s) {
            r0[tid] += r0[tid + s];
            r1[tid] += r1[tid + s];
            r2[tid] += r2[tid + s];
        }
        __syncthreads();
    }

    if (tid == 0) {
        const float inv = 1.f / r0[0];
        const float xc = r1[0] * inv;
        const float yc = r2[0] * inv;

        const int px = (int)rintf(fminf(fmaxf(xc, 0.f), 63.f));
        const int py = (int)rintf(fminf(fmaxf(yc, 0.f), 63.f));
        int pxs[5], pys[5]; bool okx[5], oky[5];
#pragma unroll
        for (int i = 0; i < 5; i++) {
            const int xs = px - 2 + i; okx[i] = (xs >= 0 && xs < WW); pxs[i] = min(max(xs, 0), 63);
            const int ys = py - 2 + i; oky[i] = (ys >= 0 && ys < HH); pys[i] = min(max(ys, 0), 63);
        }
        float pv[25];
        float pm = -1e30f;
        for (int j = 0; j < 5; j++)
            for (int i = 0; i < 5; i++) {
                const float v = hm[pys[j] * WW + pxs[i]];
                pv[j * 5 + i] = v;
                if (okx[i] && oky[j]) pm = fmaxf(pm, v);
            }
        float ws = 0.f, rx = 0.f, ry = 0.f;
        for (int j = 0; j < 5; j++)
            for (int i = 0; i < 5; i++)
                if (okx[i] && oky[j]) {
                    const float e = expf(pv[j * 5 + i] - pm);
                    ws += e;
                    rx += e * (float)pxs[i];
                    ry += e * (float)pys[j];
                }
        rx /= ws; ry /= ws;

        const float a   = 1.f / (1.f + expf(-alpha_p[0]));
        const float fwv = 1.f / (1.f + expf(-fusion_p[0]));
        float cx = a * xc + (1.f - a) * rx;
        float cy = a * yc + (1.f - a) * ry;

        const float ix = fminf(fmaxf(cx, 0.f), 63.f);
        const float iy = fminf(fmaxf(cy, 0.f), 63.f);
        const float x0f = floorf(ix), y0f = floorf(iy);
        const float wx = ix - x0f, wy = iy - y0f;
        const int x0 = min(max((int)x0f, 0), 63);
        const int y0 = min(max((int)y0f, 0), 63);
        const int x1 = min(x0 + 1, 63);
        const int y1 = min(y0 + 1, 63);
        const float* ob = off + (size_t)bk * 2 * NPIX;
        float sv[2];
#pragma unroll
        for (int ch = 0; ch < 2; ch++) {
            const float* o = ob + ch * NPIX;
            const float v00 = o[y0 * WW + x0], v01 = o[y0 * WW + x1];
            const float v10 = o[y1 * WW + x0], v11 = o[y1 * WW + x1];
            sv[ch] = (1.f - wy) * ((1.f - wx) * v00 + wx * v01)
                   + wy * ((1.f - wx) * v10 + wx * v11);
        }
        cx += fwv * sv[0];
        cy += fwv * sv[1];

        coords_out[bk * 2 + 0] = cx;
        coords_out[bk * 2 + 1] = cy;
        scores_out[bk] = m;
        if (bk == 0) fw_out[0] = fwv;
    }
}

// ---------------------------------------------------------------------------
extern "C" void kernel_launch(void* const* d_in, const int* in_sizes, int n_in,
                              void* d_out, int out_size)
{
    const float* x    = (const float*)d_in[0];
    const float* w_s1 = (const float*)d_in[1];
    const float* g_s1 = (const float*)d_in[2];
    const float* b_s1 = (const float*)d_in[3];
    const float* w_s2 = (const float*)d_in[4];
    const float* g_s2 = (const float*)d_in[5];
    const float* b_s2 = (const float*)d_in[6];
    const float* w_h1 = (const float*)d_in[7];
    const float* g_h1 = (const float*)d_in[8];
    const float* b_h1 = (const float*)d_in[9];
    const float* w_h2 = (const float*)d_in[10];
    const float* c_h2 = (const float*)d_in[11];
    const float* w_o1 = (const float*)d_in[12];
    const float* g_o1 = (const float*)d_in[13];
    const float* b_o1 = (const float*)d_in[14];
    const float* w_o2 = (const float*)d_in[15];
    const float* c_o2 = (const float*)d_in[16];
    const float* w_v1 = (const float*)d_in[17];
    const float* g_v1 = (const float*)d_in[18];
    const float* b_v1 = (const float*)d_in[19];
    const float* w_v2 = (const float*)d_in[20];
    const float* c_v2 = (const float*)d_in[21];
    const float* alpha  = (const float*)d_in[22];
    const float* fusion = (const float*)d_in[23];

    float* out    = (float*)d_out;
    float* heat   = out;
    float* offp   = out + 2228224;
    float* varp   = out + 6684672;
    float* fwp    = out + 8912896;
    float* coords = out + 8912897;
    float* scores = out + 8913985;

    ushort_t *xh, *xl, *ah, *al, *sh, *sl, *th, *tl, *wh, *wl;
    cudaGetSymbolAddress((void**)&xh, g_xh);
    cudaGetSymbolAddress((void**)&xl, g_xl);
    cudaGetSymbolAddress((void**)&ah, g_ah);
    cudaGetSymbolAddress((void**)&al, g_al);
    cudaGetSymbolAddress((void**)&sh, g_sh);
    cudaGetSymbolAddress((void**)&sl, g_sl);
    cudaGetSymbolAddress((void**)&th, g_th);
    cudaGetSymbolAddress((void**)&tl, g_tl);
    cudaGetSymbolAddress((void**)&wh, g_wh);
    cudaGetSymbolAddress((void**)&wl, g_wl);

    const int SMEM = 2 * 98304;
    cudaFuncSetAttribute(conv3x3_mma<256, 3>,
        cudaFuncAttributeMaxDynamicSharedMemorySize, SMEM);
    cudaFuncSetAttribute(conv3x3_mma<256, 2>,
        cudaFuncAttributeMaxDynamicSharedMemorySize, SMEM);
    cudaFuncSetAttribute(conv3x3_mma<128, 2>,
        cudaFuncAttributeMaxDynamicSharedMemorySize, SMEM);

    const size_t O_S1 = 0, O_S2 = 589824, O_H1 = 1179648, O_O1 = 1769472, O_V1 = 2359296;

    dim3 blk(256);
    nchw2nhwc_split<<<dim3(1024, BATCH), blk>>>(x, xh, xl);
    wprep<<<2304, blk>>>(w_s1, wh + O_S1, wl + O_S1, 256);
    wprep<<<2304, blk>>>(w_s2, wh + O_S2, wl + O_S2, 256);
    wprep<<<2304, blk>>>(w_h1, wh + O_H1, wl + O_H1, 256);
    wprep<<<2304, blk>>>(w_o1, wh + O_O1, wl + O_O1, 256);
    wprep<<<1152, blk>>>(w_v1, wh + O_V1, wl + O_V1, 128);

    dim3 cblk(512);
    dim3 g256(32, BATCH);   // M=128 pixel tiles
    dim3 g128(16, BATCH);   // M=256 pixel tiles

    // stem: fp16 3-pass (near-fp32 exact)
    conv3x3_mma<256, 3><<<g256, cblk, SMEM>>>(xh, xl, wh + O_S1, wl + O_S1, g_s1, b_s1, ah, al);
    conv3x3_mma<256, 3><<<g256, cblk, SMEM>>>(ah, al, wh + O_S2, wl + O_S2, g_s2, b_s2, sh, sl);

    // heatmap head: 2-pass conv + PPT conv1x1
    conv3x3_mma<256, 2><<<g256, cblk, SMEM>>>(sh, sl, wh + O_H1, wl + O_H1, g_h1, b_h1, th, tl);
    conv1x1_k<256, 17, 4, false><<<128, blk>>>(th, tl, w_h2, c_h2, heat);

    // offset head
    conv3x3_mma<256, 2><<<g256, cblk, SMEM>>>(sh, sl, wh + O_O1, wl + O_O1, g_o1, b_o1, th, tl);
    conv1x1_k<256, 34, 2, false><<<256, blk>>>(th, tl, w_o2, c_o2, offp);

    // variance head
    conv3x3_mma<128, 2><<<g128, cblk, SMEM>>>(sh, sl, wh + O_V1, wl + O_V1, g_v1, b_v1, th, tl);
    conv1x1_k<128, 17, 4, true><<<128, blk>>>(th, tl, w_v2, c_v2, varp);

    // fused soft-argmax + refine + offset sampling
    postproc_k<<<BATCH * KPTS, blk>>>(heat, offp, alpha, fusion, fwp, coords, scores);
}

// round 9
// speedup vs baseline: 2.3969x; 1.1804x over previous
#include <cuda_runtime.h>
#include <cuda_fp16.h>
#include <math.h>

#define CIN   256
#define HH    64
#define WW    64
#define NPIX  4096
#define BATCH 32
#define KPTS  17

typedef unsigned short ushort_t;
typedef unsigned int   uint_t;

// ---------------------------------------------------------------------------
// Scratch (device globals — no runtime allocation allowed)
// Activations NHWC fp16 hi/lo: addr = (n*4096 + p)*C + ci
// ---------------------------------------------------------------------------
__device__ __align__(1024) ushort_t g_xh[33554432];
__device__ __align__(1024) ushort_t g_xl[33554432];
__device__ __align__(1024) ushort_t g_ah[33554432];
__device__ __align__(1024) ushort_t g_al[33554432];
__device__ __align__(1024) ushort_t g_sh[33554432];
__device__ __align__(1024) ushort_t g_sl[33554432];
__device__ __align__(1024) ushort_t g_th[33554432];
__device__ __align__(1024) ushort_t g_tl[33554432];
__device__ __align__(1024) ushort_t g_wh[2654208];
__device__ __align__(1024) ushort_t g_wl[2654208];

// ---------------------------------------------------------------------------
__device__ __forceinline__ unsigned smem_to_u32(const void* p) {
    unsigned a;
    asm("{ .reg .u64 t; cvta.to.shared.u64 t, %1; cvt.u32.u64 %0, t; }"
        : "=r"(a) : "l"(p));
    return a;
}
__device__ __forceinline__ ushort_t f2h(float v) {
    __half h = __float2half_rn(v);
    return *(ushort_t*)&h;
}
__device__ __forceinline__ float h2f(ushort_t u) {
    __half h = *(__half*)&u;
    return __half2float(h);
}
__device__ __forceinline__ void ldmatrix_x4(uint_t* r, unsigned addr) {
    asm volatile("ldmatrix.sync.aligned.m8n8.x4.shared.b16 {%0,%1,%2,%3}, [%4];"
                 : "=r"(r[0]), "=r"(r[1]), "=r"(r[2]), "=r"(r[3]) : "r"(addr));
}
__device__ __forceinline__ void mma16816(float* c, const uint_t* a, const uint_t* b) {
    asm volatile(
        "mma.sync.aligned.m16n8k16.row.col.f32.f16.f16.f32 "
        "{%0,%1,%2,%3}, {%4,%5,%6,%7}, {%8,%9}, {%0,%1,%2,%3};"
        : "+f"(c[0]), "+f"(c[1]), "+f"(c[2]), "+f"(c[3])
        : "r"(a[0]), "r"(a[1]), "r"(a[2]), "r"(a[3]), "r"(b[0]), "r"(b[1]));
}
__device__ __forceinline__ void cp16(unsigned dst, const void* src, unsigned sz) {
    asm volatile("cp.async.cg.shared.global [%0], [%1], 16, %2;"
                 :: "r"(dst), "l"(src), "r"(sz) : "memory");
}
__device__ __forceinline__ void cp_commit() {
    asm volatile("cp.async.commit_group;" ::: "memory");
}

// ---------------------------------------------------------------------------
// NCHW fp32 -> NHWC fp16 hi/lo split (tiled 32x32 transpose)
// ---------------------------------------------------------------------------
__global__ __launch_bounds__(256) void nchw2nhwc_split(
    const float* __restrict__ x, ushort_t* __restrict__ h,
    ushort_t* __restrict__ l)
{
    __shared__ float t[32][33];
    const int n  = blockIdx.y;
    const int cb = blockIdx.x >> 7;
    const int pb = blockIdx.x & 127;
    const int lane = threadIdx.x & 31, wr = threadIdx.x >> 5;

    const float* src = x + ((size_t)n * 256 + cb * 32) * 4096 + pb * 32;
#pragma unroll
    for (int j = 0; j < 4; j++) {
        const int ci = wr * 4 + j;
        t[ci][lane] = src[(size_t)ci * 4096 + lane];
    }
    __syncthreads();
#pragma unroll
    for (int j = 0; j < 4; j++) {
        const int p = wr * 4 + j;
        const float v = t[lane][p];
        const ushort_t hb = f2h(v);
        const size_t o = ((size_t)n * 4096 + pb * 32 + p) * 256 + cb * 32 + lane;
        h[o] = hb;
        l[o] = f2h(v - h2f(hb));
    }
}

// ---------------------------------------------------------------------------
// Weight prep: reorder w[co][ci][ky][kx] into 36 chunk-tiles (cc = cb*9 + s),
// each [co][64 ci] K-major with SW128 swizzle baked in, fp16 hi/lo split.
// ---------------------------------------------------------------------------
__global__ __launch_bounds__(256) void wprep(
    const float* __restrict__ w, ushort_t* __restrict__ wh,
    ushort_t* __restrict__ wl, int CO)
{
    int idx = blockIdx.x * 256 + threadIdx.x;
    int co = idx / 2304, r = idx % 2304;
    int ci = r / 9, s = r % 9;
    int cb = ci >> 6, cii = ci & 63;
    int cc = cb * 9 + s;
    unsigned off = (unsigned)(co * 128 + cii * 2) ^ (unsigned)((co & 7) << 4);
    size_t dst = (size_t)cc * CO * 64 + (off >> 1);
    float v = w[idx];
    ushort_t hb = f2h(v);
    wh[dst] = hb;
    wl[dst] = f2h(v - h2f(hb));
}

// ---------------------------------------------------------------------------
// 3x3 SAME conv + BN + ReLU, fp16 hi/lo split mma.sync, NHWC, cp.async pipe.
// PASSES=3: AhBh + AhBl + AlBh (err ~2^-22). PASSES=2: AhBh + AlBh (err ~2^-11).
// 512 threads. COUT=256: M=128px x N=256; COUT=128: M=256px x N=128.
// ---------------------------------------------------------------------------
template <int COUT, int PASSES>
__global__ __launch_bounds__(512, 1) void conv3x3_mma(
    const ushort_t* __restrict__ inh, const ushort_t* __restrict__ inl,
    const ushort_t* __restrict__ wh,  const ushort_t* __restrict__ wl,
    const float* __restrict__ gma, const float* __restrict__ bta,
    ushort_t* __restrict__ outh, ushort_t* __restrict__ outl)
{
    constexpr int MPIX   = (COUT == 256) ? 128 : 256;
    constexpr int ROWS   = MPIX / 64;
    constexpr int WM     = MPIX / 64;
    constexpr int ABYTES = MPIX * 128;
    constexpr int BBYTES = COUT * 128;
    constexpr int BPL    = (PASSES == 3) ? 2 : 1;
    constexpr int STAGE  = 2 * ABYTES + BPL * BBYTES;

    extern __shared__ __align__(1024) char smem[];
    const unsigned sb = smem_to_u32(smem);
    const int tid = threadIdx.x, wid = tid >> 5, lane = tid & 31;
    const int n = blockIdx.y, r0 = blockIdx.x * ROWS;

    const int warp_m = wid % WM;
    const int warp_n = wid / WM;

    float acc[4][4][4];
#pragma unroll
    for (int mt = 0; mt < 4; mt++)
#pragma unroll
        for (int nt = 0; nt < 4; nt++)
#pragma unroll
            for (int c = 0; c < 4; c++) acc[mt][nt][c] = 0.f;

    auto issue = [&](int cc, int st) {
        const int cb = cc / 9, s = cc - cb * 9;
        const int ky = s / 3, kx = s - ky * 3;
        const unsigned sbase = sb + st * STAGE;
#pragma unroll
        for (int i = tid; i < MPIX * 16; i += 512) {
            const int plane = i / (MPIX * 8);
            const int r = i - plane * (MPIX * 8);
            const int px = r >> 3, g = r & 7;
            const int row = r0 + (px >> 6) + ky - 1;
            const int col = (px & 63) + kx - 1;
            const bool ok = (row >= 0) && (row < HH) && (col >= 0) && (col < WW);
            const ushort_t* src = (plane ? inl : inh)
                + ((size_t)(n * 4096 + (ok ? row * 64 + col : 0))) * 256
                + cb * 64 + g * 8;
            const unsigned dst = sbase + plane * ABYTES
                + (((unsigned)(px * 128 + g * 16)) ^ ((unsigned)((px & 7) << 4)));
            cp16(dst, src, ok ? 16u : 0u);
        }
#pragma unroll
        for (int i = tid; i < COUT * 8 * BPL; i += 512) {
            const int plane = i / (COUT * 8);
            const int r = i - plane * (COUT * 8);
            const ushort_t* src = (plane ? wl : wh) + (size_t)cc * COUT * 64 + r * 8;
            const unsigned dst = sbase + 2 * ABYTES + plane * BBYTES + r * 16;
            cp16(dst, src, 16);
        }
        cp_commit();
    };

    issue(0, 0);

    for (int cc = 0; cc < 36; cc++) {
        const int cur = cc & 1;
        if (cc < 35) {
            issue(cc + 1, cur ^ 1);
            asm volatile("cp.async.wait_group 1;" ::: "memory");
        } else {
            asm volatile("cp.async.wait_group 0;" ::: "memory");
        }
        __syncthreads();

        const unsigned ab = sb + cur * STAGE;
        const unsigned bb = ab + 2 * ABYTES;
#pragma unroll
        for (int k4 = 0; k4 < 4; k4++) {
            const unsigned kb = (unsigned)(k4 * 32);
            uint_t Bh[4][2], Bl[4][2];
            {
                const int j = lane & 7, g = lane >> 3;
                const int ntp = g >> 1, kh = g & 1;
#pragma unroll
                for (int q = 0; q < 2; q++) {
                    const unsigned row = (unsigned)(warp_n * 32 + (q * 2 + ntp) * 8 + j);
                    const unsigned off = (row * 128 + kb + (unsigned)(kh * 16))
                                         ^ ((unsigned)j << 4);
                    uint_t r[4];
                    ldmatrix_x4(r, bb + off);
                    Bh[q*2][0] = r[0]; Bh[q*2][1] = r[1];
                    Bh[q*2+1][0] = r[2]; Bh[q*2+1][1] = r[3];
                    if (PASSES == 3) {
                        ldmatrix_x4(r, bb + BBYTES + off);
                        Bl[q*2][0] = r[0]; Bl[q*2][1] = r[1];
                        Bl[q*2+1][0] = r[2]; Bl[q*2+1][1] = r[3];
                    }
                }
            }
#pragma unroll
            for (int mt = 0; mt < 4; mt++) {
                const unsigned arow = (unsigned)(warp_m * 64 + mt * 16 + (lane & 15));
                const unsigned off = (arow * 128 + kb + (unsigned)((lane >> 4) << 4))
                                     ^ ((arow & 7) << 4);
                uint_t A[4];
                ldmatrix_x4(A, ab + off);                 // Ah
#pragma unroll
                for (int nt = 0; nt < 4; nt++) {
                    mma16816(acc[mt][nt], A, Bh[nt]);     // Ah*Bh
                    if (PASSES == 3)
                        mma16816(acc[mt][nt], A, Bl[nt]); // Ah*Bl
                }
            }
#pragma unroll
            for (int mt = 0; mt < 4; mt++) {
                const unsigned arow = (unsigned)(warp_m * 64 + mt * 16 + (lane & 15));
                const unsigned off = (arow * 128 + kb + (unsigned)((lane >> 4) << 4))
                                     ^ ((arow & 7) << 4);
                uint_t A[4];
                ldmatrix_x4(A, ab + ABYTES + off);        // Al
#pragma unroll
                for (int nt = 0; nt < 4; nt++)
                    mma16816(acc[mt][nt], A, Bh[nt]);     // Al*Bh
            }
        }
        __syncthreads();
    }

    // ---- epilogue: BN + ReLU + fp16 hi/lo split, NHWC packed u32 stores ----
    const float rs = rsqrtf(1.0f + 1e-5f);
    float sc[4][2], bs[4][2];
#pragma unroll
    for (int nt = 0; nt < 4; nt++)
#pragma unroll
        for (int j = 0; j < 2; j++) {
            const int co = warp_n * 32 + nt * 8 + (lane & 3) * 2 + j;
            sc[nt][j] = gma[co] * rs;
            bs[nt][j] = bta[co];
        }

#pragma unroll
    for (int mt = 0; mt < 4; mt++)
#pragma unroll
        for (int ch = 0; ch < 2; ch++) {
            const int p = warp_m * 64 + mt * 16 + (lane >> 2) + ch * 8;
            const size_t base = ((size_t)n * 4096 + r0 * 64 + p) * COUT
                              + warp_n * 32 + (lane & 3) * 2;
#pragma unroll
            for (int nt = 0; nt < 4; nt++) {
                const float v0 = fmaxf(fmaf(acc[mt][nt][ch*2+0], sc[nt][0], bs[nt][0]), 0.f);
                const float v1 = fmaxf(fmaf(acc[mt][nt][ch*2+1], sc[nt][1], bs[nt][1]), 0.f);
                const ushort_t h0 = f2h(v0), h1 = f2h(v1);
                const uint_t ph = (uint_t)h0 | ((uint_t)h1 << 16);
                const uint_t pl = (uint_t)f2h(v0 - h2f(h0))
                                | ((uint_t)f2h(v1 - h2f(h1)) << 16);
                *(uint_t*)(outh + base + nt * 8) = ph;
                *(uint_t*)(outl + base + nt * 8) = pl;
            }
        }
}

// ---------------------------------------------------------------------------
// 1x1 conv head from NHWC fp16 hi/lo; fp32 weights/accum; NCHW fp32 out.
// PPT pixels per thread: each broadcast-LDS weight feeds PPT FMAs.
// ---------------------------------------------------------------------------
template <int CI, int CO, int PPT, bool SOFTPLUS>
__global__ __launch_bounds__(256) void conv1x1_k(
    const ushort_t* __restrict__ inh, const ushort_t* __restrict__ inl,
    const float* __restrict__ w, const float* __restrict__ bias,
    float* __restrict__ out)
{
    __shared__ float s_w[CI * CO];   // [ci][co]
    const int tid = threadIdx.x;
    for (int i = tid; i < CI * CO; i += 256)
        s_w[(i % CI) * CO + i / CI] = w[i];
    __syncthreads();

    const int pid0 = (blockIdx.x * 256 + tid) * PPT;
    const int n = pid0 >> 12;

    float acc[PPT][CO];
#pragma unroll
    for (int q = 0; q < PPT; q++)
#pragma unroll
        for (int c = 0; c < CO; c++) acc[q][c] = 0.f;

    for (int u = 0; u < CI / 8; u++) {
        float v[PPT][8];
#pragma unroll
        for (int q = 0; q < PPT; q++) {
            const uint4 qh = *(const uint4*)(inh + (size_t)(pid0 + q) * CI + u * 8);
            const uint4 ql = *(const uint4*)(inl + (size_t)(pid0 + q) * CI + u * 8);
            const uint_t hw[4] = {qh.x, qh.y, qh.z, qh.w};
            const uint_t lw[4] = {ql.x, ql.y, ql.z, ql.w};
#pragma unroll
            for (int g = 0; g < 4; g++) {
                v[q][g*2+0] = h2f((ushort_t)hw[g]) + h2f((ushort_t)lw[g]);
                v[q][g*2+1] = h2f((ushort_t)(hw[g] >> 16)) + h2f((ushort_t)(lw[g] >> 16));
            }
        }
#pragma unroll
        for (int g = 0; g < 8; g++) {
            const int ci = u * 8 + g;
#pragma unroll
            for (int co = 0; co < CO; co++) {
                const float wv = s_w[ci * CO + co];
#pragma unroll
                for (int q = 0; q < PPT; q++)
                    acc[q][co] = fmaf(v[q][g], wv, acc[q][co]);
            }
        }
    }
#pragma unroll
    for (int q = 0; q < PPT; q++) {
        const int p = (pid0 + q) & 4095;
#pragma unroll
        for (int co = 0; co < CO; co++) {
            float o = acc[q][co] + bias[co];
            if (SOFTPLUS)
                o = (o > 0.f) ? (o + log1pf(expf(-o))) : log1pf(expf(o));
            out[((size_t)n * CO + co) * NPIX + p] = o;
        }
    }
}

// ---------------------------------------------------------------------------
// Fused postprocessing (reads NCHW heat/off)
// ---------------------------------------------------------------------------
__global__ __launch_bounds__(256) void postproc_k(
    const float* __restrict__ heat, const float* __restrict__ off,
    const float* __restrict__ alpha_p, const float* __restrict__ fusion_p,
    float* __restrict__ fw_out, float* __restrict__ coords_out,
    float* __restrict__ scores_out)
{
    __shared__ float r0[256], r1[256], r2[256];
    const int bk  = blockIdx.x;
    const int tid = threadIdx.x;
    const float* hm = heat + (size_t)bk * NPIX;

    float lm = -1e30f;
#pragma unroll
    for (int i = 0; i < 16; i++) lm = fmaxf(lm, hm[tid + i * 256]);
    r0[tid] = lm;
    __syncthreads();
    for (int s = 128; s > 0; s >>= 1) {
        if (tid < s) r0[tid] = fmaxf(r0[tid], r0[tid + s]);
        __syncthreads();
    }
    const float m = r0[0];
    __syncthreads();

    float se = 0.f, sx = 0.f, sy = 0.f;
#pragma unroll
    for (int i = 0; i < 16; i++) {
        const int idx = tid + i * 256;
        const float e = expf(hm[idx] - m);
        se += e;
        sx += e * (float)(idx & 63);
        sy += e * (float)(idx >> 6);
    }
    r0[tid] = se; r1[tid] = sx; r2[tid] = sy;
    __syncthreads();
    for (int s = 128; s > 0; s >>= 1) {
        if (tid < s) {
            r0[tid] += r0[tid + s];
            r1[tid] += r1[tid + s];
            r2[tid] += r2[tid + s];
        }
        __syncthreads();
    }

    if (tid == 0) {
        const float inv = 1.f / r0[0];
        const float xc = r1[0] * inv;
        const float yc = r2[0] * inv;

        const int px = (int)rintf(fminf(fmaxf(xc, 0.f), 63.f));
        const int py = (int)rintf(fminf(fmaxf(yc, 0.f), 63.f));
        int pxs[5], pys[5]; bool okx[5], oky[5];
#pragma unroll
        for (int i = 0; i < 5; i++) {
            const int xs = px - 2 + i; okx[i] = (xs >= 0 && xs < WW); pxs[i] = min(max(xs, 0), 63);
            const int ys = py - 2 + i; oky[i] = (ys >= 0 && ys < HH); pys[i] = min(max(ys, 0), 63);
        }
        float pv[25];
        float pm = -1e30f;
        for (int j = 0; j < 5; j++)
            for (int i = 0; i < 5; i++) {
                const float v = hm[pys[j] * WW + pxs[i]];
                pv[j * 5 + i] = v;
                if (okx[i] && oky[j]) pm = fmaxf(pm, v);
            }
        float ws = 0.f, rx = 0.f, ry = 0.f;
        for (int j = 0; j < 5; j++)
            for (int i = 0; i < 5; i++)
                if (okx[i] && oky[j]) {
                    const float e = expf(pv[j * 5 + i] - pm);
                    ws += e;
                    rx += e * (float)pxs[i];
                    ry += e * (float)pys[j];
                }
        rx /= ws; ry /= ws;

        const float a   = 1.f / (1.f + expf(-alpha_p[0]));
        const float fwv = 1.f / (1.f + expf(-fusion_p[0]));
        float cx = a * xc + (1.f - a) * rx;
        float cy = a * yc + (1.f - a) * ry;

        const float ix = fminf(fmaxf(cx, 0.f), 63.f);
        const float iy = fminf(fmaxf(cy, 0.f), 63.f);
        const float x0f = floorf(ix), y0f = floorf(iy);
        const float wx = ix - x0f, wy = iy - y0f;
        const int x0 = min(max((int)x0f, 0), 63);
        const int y0 = min(max((int)y0f, 0), 63);
        const int x1 = min(x0 + 1, 63);
        const int y1 = min(y0 + 1, 63);
        const float* ob = off + (size_t)bk * 2 * NPIX;
        float sv[2];
#pragma unroll
        for (int ch = 0; ch < 2; ch++) {
            const float* o = ob + ch * NPIX;
            const float v00 = o[y0 * WW + x0], v01 = o[y0 * WW + x1];
            const float v10 = o[y1 * WW + x0], v11 = o[y1 * WW + x1];
            sv[ch] = (1.f - wy) * ((1.f - wx) * v00 + wx * v01)
                   + wy * ((1.f - wx) * v10 + wx * v11);
        }
        cx += fwv * sv[0];
        cy += fwv * sv[1];

        coords_out[bk * 2 + 0] = cx;
        coords_out[bk * 2 + 1] = cy;
        scores_out[bk] = m;
        if (bk == 0) fw_out[0] = fwv;
    }
}

// ---------------------------------------------------------------------------
extern "C" void kernel_launch(void* const* d_in, const int* in_sizes, int n_in,
                              void* d_out, int out_size)
{
    const float* x    = (const float*)d_in[0];
    const float* w_s1 = (const float*)d_in[1];
    const float* g_s1 = (const float*)d_in[2];
    const float* b_s1 = (const float*)d_in[3];
    const float* w_s2 = (const float*)d_in[4];
    const float* g_s2 = (const float*)d_in[5];
    const float* b_s2 = (const float*)d_in[6];
    const float* w_h1 = (const float*)d_in[7];
    const float* g_h1 = (const float*)d_in[8];
    const float* b_h1 = (const float*)d_in[9];
    const float* w_h2 = (const float*)d_in[10];
    const float* c_h2 = (const float*)d_in[11];
    const float* w_o1 = (const float*)d_in[12];
    const float* g_o1 = (const float*)d_in[13];
    const float* b_o1 = (const float*)d_in[14];
    const float* w_o2 = (const float*)d_in[15];
    const float* c_o2 = (const float*)d_in[16];
    const float* w_v1 = (const float*)d_in[17];
    const float* g_v1 = (const float*)d_in[18];
    const float* b_v1 = (const float*)d_in[19];
    const float* w_v2 = (const float*)d_in[20];
    const float* c_v2 = (const float*)d_in[21];
    const float* alpha  = (const float*)d_in[22];
    const float* fusion = (const float*)d_in[23];

    float* out    = (float*)d_out;
    float* heat   = out;
    float* offp   = out + 2228224;
    float* varp   = out + 6684672;
    float* fwp    = out + 8912896;
    float* coords = out + 8912897;
    float* scores = out + 8913985;

    ushort_t *xh, *xl, *ah, *al, *sh, *sl, *th, *tl, *wh, *wl;
    cudaGetSymbolAddress((void**)&xh, g_xh);
    cudaGetSymbolAddress((void**)&xl, g_xl);
    cudaGetSymbolAddress((void**)&ah, g_ah);
    cudaGetSymbolAddress((void**)&al, g_al);
    cudaGetSymbolAddress((void**)&sh, g_sh);
    cudaGetSymbolAddress((void**)&sl, g_sl);
    cudaGetSymbolAddress((void**)&th, g_th);
    cudaGetSymbolAddress((void**)&tl, g_tl);
    cudaGetSymbolAddress((void**)&wh, g_wh);
    cudaGetSymbolAddress((void**)&wl, g_wl);

    // 2-pass stages: conv256 = 2*16384 + 32768 = 64KB; conv128 = 2*32768 + 16384 = 80KB
    const int SMEM256 = 2 * (2 * 16384 + 32768);
    const int SMEM128 = 2 * (2 * 32768 + 16384);
    cudaFuncSetAttribute(conv3x3_mma<256, 2>,
        cudaFuncAttributeMaxDynamicSharedMemorySize, SMEM256);
    cudaFuncSetAttribute(conv3x3_mma<128, 2>,
        cudaFuncAttributeMaxDynamicSharedMemorySize, SMEM128);

    const size_t O_S1 = 0, O_S2 = 589824, O_H1 = 1179648, O_O1 = 1769472, O_V1 = 2359296;

    dim3 blk(256);
    nchw2nhwc_split<<<dim3(1024, BATCH), blk>>>(x, xh, xl);
    wprep<<<2304, blk>>>(w_s1, wh + O_S1, wl + O_S1, 256);
    wprep<<<2304, blk>>>(w_s2, wh + O_S2, wl + O_S2, 256);
    wprep<<<2304, blk>>>(w_h1, wh + O_H1, wl + O_H1, 256);
    wprep<<<2304, blk>>>(w_o1, wh + O_O1, wl + O_O1, 256);
    wprep<<<1152, blk>>>(w_v1, wh + O_V1, wl + O_V1, 128);

    dim3 cblk(512);
    dim3 g256(32, BATCH);   // M=128 pixel tiles
    dim3 g128(16, BATCH);   // M=256 pixel tiles

    // stem: 2-pass (exact activations x fp16 weights)
    conv3x3_mma<256, 2><<<g256, cblk, SMEM256>>>(xh, xl, wh + O_S1, wl + O_S1, g_s1, b_s1, ah, al);
    conv3x3_mma<256, 2><<<g256, cblk, SMEM256>>>(ah, al, wh + O_S2, wl + O_S2, g_s2, b_s2, sh, sl);

    // heatmap head
    conv3x3_mma<256, 2><<<g256, cblk, SMEM256>>>(sh, sl, wh + O_H1, wl + O_H1, g_h1, b_h1, th, tl);
    conv1x1_k<256, 17, 4, false><<<128, blk>>>(th, tl, w_h2, c_h2, heat);

    // offset head
    conv3x3_mma<256, 2><<<g256, cblk, SMEM256>>>(sh, sl, wh + O_O1, wl + O_O1, g_o1, b_o1, th, tl);
    conv1x1_k<256, 34, 2, false><<<256, blk>>>(th, tl, w_o2, c_o2, offp);

    // variance head
    conv3x3_mma<128, 2><<<g128, cblk, SMEM128>>>(sh, sl, wh + O_V1, wl + O_V1, g_v1, b_v1, th, tl);
    conv1x1_k<128, 17, 4, true><<<128, blk>>>(th, tl, w_v2, c_v2, varp);

    // fused soft-argmax + refine + offset sampling
    postproc_k<<<BATCH * KPTS, blk>>>(heat, offp, alpha, fusion, fwp, coords, scores);
}

// round 11
// speedup vs baseline: 2.4632x; 1.0277x over previous
#include <cuda_runtime.h>
#include <cuda_fp16.h>
#include <math.h>

#define CIN   256
#define HH    64
#define WW    64
#define NPIX  4096
#define BATCH 32
#define KPTS  17

typedef unsigned short ushort_t;
typedef unsigned int   uint_t;

// ---------------------------------------------------------------------------
// Scratch (device globals — no runtime allocation allowed)
// Activations NHWC fp16 hi/lo: addr = (n*4096 + p)*C + ci
// ---------------------------------------------------------------------------
__device__ __align__(1024) ushort_t g_xh[33554432];
__device__ __align__(1024) ushort_t g_xl[33554432];
__device__ __align__(1024) ushort_t g_ah[33554432];
__device__ __align__(1024) ushort_t g_al[33554432];
__device__ __align__(1024) ushort_t g_sh[33554432];
__device__ __align__(1024) ushort_t g_sl[33554432];
__device__ __align__(1024) ushort_t g_th[33554432];
__device__ __align__(1024) ushort_t g_tl[33554432];
__device__ __align__(1024) ushort_t g_wh[2654208];
__device__ __align__(1024) ushort_t g_wl[2654208];

// ---------------------------------------------------------------------------
__device__ __forceinline__ unsigned smem_to_u32(const void* p) {
    unsigned a;
    asm("{ .reg .u64 t; cvta.to.shared.u64 t, %1; cvt.u32.u64 %0, t; }"
        : "=r"(a) : "l"(p));
    return a;
}
__device__ __forceinline__ ushort_t f2h(float v) {
    __half h = __float2half_rn(v);
    return *(ushort_t*)&h;
}
__device__ __forceinline__ float h2f(ushort_t u) {
    __half h = *(__half*)&u;
    return __half2float(h);
}
__device__ __forceinline__ void ldmatrix_x4(uint_t* r, unsigned addr) {
    asm volatile("ldmatrix.sync.aligned.m8n8.x4.shared.b16 {%0,%1,%2,%3}, [%4];"
                 : "=r"(r[0]), "=r"(r[1]), "=r"(r[2]), "=r"(r[3]) : "r"(addr));
}
__device__ __forceinline__ void mma16816(float* c, const uint_t* a, const uint_t* b) {
    asm volatile(
        "mma.sync.aligned.m16n8k16.row.col.f32.f16.f16.f32 "
        "{%0,%1,%2,%3}, {%4,%5,%6,%7}, {%8,%9}, {%0,%1,%2,%3};"
        : "+f"(c[0]), "+f"(c[1]), "+f"(c[2]), "+f"(c[3])
        : "r"(a[0]), "r"(a[1]), "r"(a[2]), "r"(a[3]), "r"(b[0]), "r"(b[1]));
}
__device__ __forceinline__ void cp16(unsigned dst, const void* src, unsigned sz) {
    asm volatile("cp.async.cg.shared.global [%0], [%1], 16, %2;"
                 :: "r"(dst), "l"(src), "r"(sz) : "memory");
}
__device__ __forceinline__ void cp_commit() {
    asm volatile("cp.async.commit_group;" ::: "memory");
}

// ---------------------------------------------------------------------------
// NCHW fp32 -> NHWC fp16 hi/lo split (tiled 32x32 transpose)
// ---------------------------------------------------------------------------
__global__ __launch_bounds__(256) void nchw2nhwc_split(
    const float* __restrict__ x, ushort_t* __restrict__ h,
    ushort_t* __restrict__ l)
{
    __shared__ float t[32][33];
    const int n  = blockIdx.y;
    const int cb = blockIdx.x >> 7;
    const int pb = blockIdx.x & 127;
    const int lane = threadIdx.x & 31, wr = threadIdx.x >> 5;

    const float* src = x + ((size_t)n * 256 + cb * 32) * 4096 + pb * 32;
#pragma unroll
    for (int j = 0; j < 4; j++) {
        const int ci = wr * 4 + j;
        t[ci][lane] = src[(size_t)ci * 4096 + lane];
    }
    __syncthreads();
#pragma unroll
    for (int j = 0; j < 4; j++) {
        const int p = wr * 4 + j;
        const float v = t[lane][p];
        const ushort_t hb = f2h(v);
        const size_t o = ((size_t)n * 4096 + pb * 32 + p) * 256 + cb * 32 + lane;
        h[o] = hb;
        l[o] = f2h(v - h2f(hb));
    }
}

// ---------------------------------------------------------------------------
// Weight prep: reorder w[co][ci][ky][kx] into 36 chunk-tiles (cc = cb*9 + s),
// each [co][64 ci] K-major with SW128 swizzle baked in, fp16 hi/lo split.
// ---------------------------------------------------------------------------
__global__ __launch_bounds__(256) void wprep(
    const float* __restrict__ w, ushort_t* __restrict__ wh,
    ushort_t* __restrict__ wl, int CO)
{
    int idx = blockIdx.x * 256 + threadIdx.x;
    int co = idx / 2304, r = idx % 2304;
    int ci = r / 9, s = r % 9;
    int cb = ci >> 6, cii = ci & 63;
    int cc = cb * 9 + s;
    unsigned off = (unsigned)(co * 128 + cii * 2) ^ (unsigned)((co & 7) << 4);
    size_t dst = (size_t)cc * CO * 64 + (off >> 1);
    float v = w[idx];
    ushort_t hb = f2h(v);
    wh[dst] = hb;
    wl[dst] = f2h(v - h2f(hb));
}

// ---------------------------------------------------------------------------
// 3x3 SAME conv + BN + ReLU, fp16 hi/lo split mma.sync, NHWC, cp.async pipe.
// PASSES=2: AhBh + AlBh (exact activations x fp16-rounded weights).
// STAGES=3: one __syncthreads per chunk (two fills always in flight).
// 512 threads. COUT=256: M=128px x N=256; COUT=128: M=256px x N=128.
// ---------------------------------------------------------------------------
template <int COUT, int PASSES, int STAGES>
__global__ __launch_bounds__(512, 1) void conv3x3_mma(
    const ushort_t* __restrict__ inh, const ushort_t* __restrict__ inl,
    const ushort_t* __restrict__ wh,  const ushort_t* __restrict__ wl,
    const float* __restrict__ gma, const float* __restrict__ bta,
    ushort_t* __restrict__ outh, ushort_t* __restrict__ outl)
{
    constexpr int MPIX   = (COUT == 256) ? 128 : 256;
    constexpr int ROWS   = MPIX / 64;
    constexpr int WM     = MPIX / 64;
    constexpr int ABYTES = MPIX * 128;
    constexpr int BBYTES = COUT * 128;
    constexpr int BPL    = (PASSES == 3) ? 2 : 1;
    constexpr int STAGE  = 2 * ABYTES + BPL * BBYTES;

    extern __shared__ __align__(1024) char smem[];
    const unsigned sb = smem_to_u32(smem);
    const int tid = threadIdx.x, wid = tid >> 5, lane = tid & 31;
    const int n = blockIdx.y, r0 = blockIdx.x * ROWS;

    const int warp_m = wid % WM;
    const int warp_n = wid / WM;

    float acc[4][4][4];
#pragma unroll
    for (int mt = 0; mt < 4; mt++)
#pragma unroll
        for (int nt = 0; nt < 4; nt++)
#pragma unroll
            for (int c = 0; c < 4; c++) acc[mt][nt][c] = 0.f;

    auto issue = [&](int cc, int st) {
        const int cb = cc / 9, s = cc - cb * 9;
        const int ky = s / 3, kx = s - ky * 3;
        const unsigned sbase = sb + st * STAGE;
#pragma unroll
        for (int i = tid; i < MPIX * 16; i += 512) {
            const int plane = i / (MPIX * 8);
            const int r = i - plane * (MPIX * 8);
            const int px = r >> 3, g = r & 7;
            const int row = r0 + (px >> 6) + ky - 1;
            const int col = (px & 63) + kx - 1;
            const bool ok = (row >= 0) && (row < HH) && (col >= 0) && (col < WW);
            const ushort_t* src = (plane ? inl : inh)
                + ((size_t)(n * 4096 + (ok ? row * 64 + col : 0))) * 256
                + cb * 64 + g * 8;
            const unsigned dst = sbase + plane * ABYTES
                + (((unsigned)(px * 128 + g * 16)) ^ ((unsigned)((px & 7) << 4)));
            cp16(dst, src, ok ? 16u : 0u);
        }
#pragma unroll
        for (int i = tid; i < COUT * 8 * BPL; i += 512) {
            const int plane = i / (COUT * 8);
            const int r = i - plane * (COUT * 8);
            const ushort_t* src = (plane ? wl : wh) + (size_t)cc * COUT * 64 + r * 8;
            const unsigned dst = sbase + 2 * ABYTES + plane * BBYTES + r * 16;
            cp16(dst, src, 16);
        }
        cp_commit();
    };

    auto compute = [&](unsigned ab) {
        const unsigned bb = ab + 2 * ABYTES;
#pragma unroll
        for (int k4 = 0; k4 < 4; k4++) {
            const unsigned kb = (unsigned)(k4 * 32);
            uint_t Bh[4][2], Bl[4][2];
            {
                const int j = lane & 7, g = lane >> 3;
                const int ntp = g >> 1, kh = g & 1;
#pragma unroll
                for (int q = 0; q < 2; q++) {
                    const unsigned row = (unsigned)(warp_n * 32 + (q * 2 + ntp) * 8 + j);
                    const unsigned off = (row * 128 + kb + (unsigned)(kh * 16))
                                         ^ ((unsigned)j << 4);
                    uint_t r[4];
                    ldmatrix_x4(r, bb + off);
                    Bh[q*2][0] = r[0]; Bh[q*2][1] = r[1];
                    Bh[q*2+1][0] = r[2]; Bh[q*2+1][1] = r[3];
                    if (PASSES == 3) {
                        ldmatrix_x4(r, bb + BBYTES + off);
                        Bl[q*2][0] = r[0]; Bl[q*2][1] = r[1];
                        Bl[q*2+1][0] = r[2]; Bl[q*2+1][1] = r[3];
                    }
                }
            }
#pragma unroll
            for (int mt = 0; mt < 4; mt++) {
                const unsigned arow = (unsigned)(warp_m * 64 + mt * 16 + (lane & 15));
                const unsigned off = (arow * 128 + kb + (unsigned)((lane >> 4) << 4))
                                     ^ ((arow & 7) << 4);
                uint_t A[4];
                ldmatrix_x4(A, ab + off);                 // Ah
#pragma unroll
                for (int nt = 0; nt < 4; nt++) {
                    mma16816(acc[mt][nt], A, Bh[nt]);     // Ah*Bh
                    if (PASSES == 3)
                        mma16816(acc[mt][nt], A, Bl[nt]); // Ah*Bl
                }
            }
#pragma unroll
            for (int mt = 0; mt < 4; mt++) {
                const unsigned arow = (unsigned)(warp_m * 64 + mt * 16 + (lane & 15));
                const unsigned off = (arow * 128 + kb + (unsigned)((lane >> 4) << 4))
                                     ^ ((arow & 7) << 4);
                uint_t A[4];
                ldmatrix_x4(A, ab + ABYTES + off);        // Al
#pragma unroll
                for (int nt = 0; nt < 4; nt++)
                    mma16816(acc[mt][nt], A, Bh[nt]);     // Al*Bh
            }
        }
    };

    if (STAGES == 3) {
        // 3-stage pipeline: one barrier per chunk, two fills in flight.
        issue(0, 0);
        issue(1, 1);
        int st = 0;
        for (int cc = 0; cc < 36; cc++) {
            if (cc < 35)
                asm volatile("cp.async.wait_group 1;" ::: "memory");
            else
                asm volatile("cp.async.wait_group 0;" ::: "memory");
            __syncthreads();
            if (cc + 2 < 36) {
                int st2 = st + 2; if (st2 >= 3) st2 -= 3;
                issue(cc + 2, st2);
            }
            compute(sb + st * STAGE);
            if (++st == 3) st = 0;
        }
    } else {
        // 2-stage double buffer (used when 3 stages exceed smem).
        issue(0, 0);
        for (int cc = 0; cc < 36; cc++) {
            const int cur = cc & 1;
            if (cc < 35) {
                issue(cc + 1, cur ^ 1);
                asm volatile("cp.async.wait_group 1;" ::: "memory");
            } else {
                asm volatile("cp.async.wait_group 0;" ::: "memory");
            }
            __syncthreads();
            compute(sb + cur * STAGE);
            __syncthreads();
        }
    }

    // ---- epilogue: BN + ReLU + fp16 hi/lo split, NHWC packed u32 stores ----
    const float rs = rsqrtf(1.0f + 1e-5f);
    float sc[4][2], bs[4][2];
#pragma unroll
    for (int nt = 0; nt < 4; nt++)
#pragma unroll
        for (int j = 0; j < 2; j++) {
            const int co = warp_n * 32 + nt * 8 + (lane & 3) * 2 + j;
            sc[nt][j] = gma[co] * rs;
            bs[nt][j] = bta[co];
        }

#pragma unroll
    for (int mt = 0; mt < 4; mt++)
#pragma unroll
        for (int ch = 0; ch < 2; ch++) {
            const int p = warp_m * 64 + mt * 16 + (lane >> 2) + ch * 8;
            const size_t base = ((size_t)n * 4096 + r0 * 64 + p) * COUT
                              + warp_n * 32 + (lane & 3) * 2;
#pragma unroll
            for (int nt = 0; nt < 4; nt++) {
                const float v0 = fmaxf(fmaf(acc[mt][nt][ch*2+0], sc[nt][0], bs[nt][0]), 0.f);
                const float v1 = fmaxf(fmaf(acc[mt][nt][ch*2+1], sc[nt][1], bs[nt][1]), 0.f);
                const ushort_t h0 = f2h(v0), h1 = f2h(v1);
                const uint_t ph = (uint_t)h0 | ((uint_t)h1 << 16);
                const uint_t pl = (uint_t)f2h(v0 - h2f(h0))
                                | ((uint_t)f2h(v1 - h2f(h1)) << 16);
                *(uint_t*)(outh + base + nt * 8) = ph;
                *(uint_t*)(outl + base + nt * 8) = pl;
            }
        }
}

// ---------------------------------------------------------------------------
// 1x1 conv head from NHWC fp16 hi/lo; fp32 weights/accum; NCHW fp32 out.
// PPT pixels per thread: each broadcast-LDS weight feeds PPT FMAs.
// ---------------------------------------------------------------------------
template <int CI, int CO, int PPT, bool SOFTPLUS>
__global__ __launch_bounds__(256) void conv1x1_k(
    const ushort_t* __restrict__ inh, const ushort_t* __restrict__ inl,
    const float* __restrict__ w, const float* __restrict__ bias,
    float* __restrict__ out)
{
    __shared__ float s_w[CI * CO];   // [ci][co]
    const int tid = threadIdx.x;
    for (int i = tid; i < CI * CO; i += 256)
        s_w[(i % CI) * CO + i / CI] = w[i];
    __syncthreads();

    const int pid0 = (blockIdx.x * 256 + tid) * PPT;
    const int n = pid0 >> 12;

    float acc[PPT][CO];
#pragma unroll
    for (int q = 0; q < PPT; q++)
#pragma unroll
        for (int c = 0; c < CO; c++) acc[q][c] = 0.f;

    for (int u = 0; u < CI / 8; u++) {
        float v[PPT][8];
#pragma unroll
        for (int q = 0; q < PPT; q++) {
            const uint4 qh = *(const uint4*)(inh + (size_t)(pid0 + q) * CI + u * 8);
            const uint4 ql = *(const uint4*)(inl + (size_t)(pid0 + q) * CI + u * 8);
            const uint_t hw[4] = {qh.x, qh.y, qh.z, qh.w};
            const uint_t lw[4] = {ql.x, ql.y, ql.z, ql.w};
#pragma unroll
            for (int g = 0; g < 4; g++) {
                v[q][g*2+0] = h2f((ushort_t)hw[g]) + h2f((ushort_t)lw[g]);
                v[q][g*2+1] = h2f((ushort_t)(hw[g] >> 16)) + h2f((ushort_t)(lw[g] >> 16));
            }
        }
#pragma unroll
        for (int g = 0; g < 8; g++) {
            const int ci = u * 8 + g;
#pragma unroll
            for (int co = 0; co < CO; co++) {
                const float wv = s_w[ci * CO + co];
#pragma unroll
                for (int q = 0; q < PPT; q++)
                    acc[q][co] = fmaf(v[q][g], wv, acc[q][co]);
            }
        }
    }
#pragma unroll
    for (int q = 0; q < PPT; q++) {
        const int p = (pid0 + q) & 4095;
#pragma unroll
        for (int co = 0; co < CO; co++) {
            float o = acc[q][co] + bias[co];
            if (SOFTPLUS)
                o = (o > 0.f) ? (o + log1pf(expf(-o))) : log1pf(expf(o));
            out[((size_t)n * CO + co) * NPIX + p] = o;
        }
    }
}

// ---------------------------------------------------------------------------
// Fused postprocessing (reads NCHW heat/off)
// ---------------------------------------------------------------------------
__global__ __launch_bounds__(256) void postproc_k(
    const float* __restrict__ heat, const float* __restrict__ off,
    const float* __restrict__ alpha_p, const float* __restrict__ fusion_p,
    float* __restrict__ fw_out, float* __restrict__ coords_out,
    float* __restrict__ scores_out)
{
    __shared__ float r0[256], r1[256], r2[256];
    const int bk  = blockIdx.x;
    const int tid = threadIdx.x;
    const float* hm = heat + (size_t)bk * NPIX;

    float lm = -1e30f;
#pragma unroll
    for (int i = 0; i < 16; i++) lm = fmaxf(lm, hm[tid + i * 256]);
    r0[tid] = lm;
    __syncthreads();
    for (int s = 128; s > 0; s >>= 1) {
        if (tid < s) r0[tid] = fmaxf(r0[tid], r0[tid + s]);
        __syncthreads();
    }
    const float m = r0[0];
    __syncthreads();

    float se = 0.f, sx = 0.f, sy = 0.f;
#pragma unroll
    for (int i = 0; i < 16; i++) {
        const int idx = tid + i * 256;
        const float e = expf(hm[idx] - m);
        se += e;
        sx += e * (float)(idx & 63);
        sy += e * (float)(idx >> 6);
    }
    r0[tid] = se; r1[tid] = sx; r2[tid] = sy;
    __syncthreads();
    for (int s = 128; s > 0; s >>= 1) {
        if (tid < s) {
            r0[tid] += r0[tid + s];
            r1[tid] += r1[tid + s];
            r2[tid] += r2[tid + s];
        }
        __syncthreads();
    }

    if (tid == 0) {
        const float inv = 1.f / r0[0];
        const float xc = r1[0] * inv;
        const float yc = r2[0] * inv;

        const int px = (int)rintf(fminf(fmaxf(xc, 0.f), 63.f));
        const int py = (int)rintf(fminf(fmaxf(yc, 0.f), 63.f));
        int pxs[5], pys[5]; bool okx[5], oky[5];
#pragma unroll
        for (int i = 0; i < 5; i++) {
            const int xs = px - 2 + i; okx[i] = (xs >= 0 && xs < WW); pxs[i] = min(max(xs, 0), 63);
            const int ys = py - 2 + i; oky[i] = (ys >= 0 && ys < HH); pys[i] = min(max(ys, 0), 63);
        }
        float pv[25];
        float pm = -1e30f;
        for (int j = 0; j < 5; j++)
            for (int i = 0; i < 5; i++) {
                const float v = hm[pys[j] * WW + pxs[i]];
                pv[j * 5 + i] = v;
                if (okx[i] && oky[j]) pm = fmaxf(pm, v);
            }
        float ws = 0.f, rx = 0.f, ry = 0.f;
        for (int j = 0; j < 5; j++)
            for (int i = 0; i < 5; i++)
                if (okx[i] && oky[j]) {
                    const float e = expf(pv[j * 5 + i] - pm);
                    ws += e;
                    rx += e * (float)pxs[i];
                    ry += e * (float)pys[j];
                }
        rx /= ws; ry /= ws;

        const float a   = 1.f / (1.f + expf(-alpha_p[0]));
        const float fwv = 1.f / (1.f + expf(-fusion_p[0]));
        float cx = a * xc + (1.f - a) * rx;
        float cy = a * yc + (1.f - a) * ry;

        const float ix = fminf(fmaxf(cx, 0.f), 63.f);
        const float iy = fminf(fmaxf(cy, 0.f), 63.f);
        const float x0f = floorf(ix), y0f = floorf(iy);
        const float wx = ix - x0f, wy = iy - y0f;
        const int x0 = min(max((int)x0f, 0), 63);
        const int y0 = min(max((int)y0f, 0), 63);
        const int x1 = min(x0 + 1, 63);
        const int y1 = min(y0 + 1, 63);
        const float* ob = off + (size_t)bk * 2 * NPIX;
        float sv[2];
#pragma unroll
        for (int ch = 0; ch < 2; ch++) {
            const float* o = ob + ch * NPIX;
            const float v00 = o[y0 * WW + x0], v01 = o[y0 * WW + x1];
            const float v10 = o[y1 * WW + x0], v11 = o[y1 * WW + x1];
            sv[ch] = (1.f - wy) * ((1.f - wx) * v00 + wx * v01)
                   + wy * ((1.f - wx) * v10 + wx * v11);
        }
        cx += fwv * sv[0];
        cy += fwv * sv[1];

        coords_out[bk * 2 + 0] = cx;
        coords_out[bk * 2 + 1] = cy;
        scores_out[bk] = m;
        if (bk == 0) fw_out[0] = fwv;
    }
}

// ---------------------------------------------------------------------------
extern "C" void kernel_launch(void* const* d_in, const int* in_sizes, int n_in,
                              void* d_out, int out_size)
{
    const float* x    = (const float*)d_in[0];
    const float* w_s1 = (const float*)d_in[1];
    const float* g_s1 = (const float*)d_in[2];
    const float* b_s1 = (const float*)d_in[3];
    const float* w_s2 = (const float*)d_in[4];
    const float* g_s2 = (const float*)d_in[5];
    const float* b_s2 = (const float*)d_in[6];
    const float* w_h1 = (const float*)d_in[7];
    const float* g_h1 = (const float*)d_in[8];
    const float* b_h1 = (const float*)d_in[9];
    const float* w_h2 = (const float*)d_in[10];
    const float* c_h2 = (const float*)d_in[11];
    const float* w_o1 = (const float*)d_in[12];
    const float* g_o1 = (const float*)d_in[13];
    const float* b_o1 = (const float*)d_in[14];
    const float* w_o2 = (const float*)d_in[15];
    const float* c_o2 = (const float*)d_in[16];
    const float* w_v1 = (const float*)d_in[17];
    const float* g_v1 = (const float*)d_in[18];
    const float* b_v1 = (const float*)d_in[19];
    const float* w_v2 = (const float*)d_in[20];
    const float* c_v2 = (const float*)d_in[21];
    const float* alpha  = (const float*)d_in[22];
    const float* fusion = (const float*)d_in[23];

    float* out    = (float*)d_out;
    float* heat   = out;
    float* offp   = out + 2228224;
    float* varp   = out + 6684672;
    float* fwp    = out + 8912896;
    float* coords = out + 8912897;
    float* scores = out + 8913985;

    ushort_t *xh, *xl, *ah, *al, *sh, *sl, *th, *tl, *wh, *wl;
    cudaGetSymbolAddress((void**)&xh, g_xh);
    cudaGetSymbolAddress((void**)&xl, g_xl);
    cudaGetSymbolAddress((void**)&ah, g_ah);
    cudaGetSymbolAddress((void**)&al, g_al);
    cudaGetSymbolAddress((void**)&sh, g_sh);
    cudaGetSymbolAddress((void**)&sl, g_sl);
    cudaGetSymbolAddress((void**)&th, g_th);
    cudaGetSymbolAddress((void**)&tl, g_tl);
    cudaGetSymbolAddress((void**)&wh, g_wh);
    cudaGetSymbolAddress((void**)&wl, g_wl);

    // conv256 stage = 2*16KB A + 32KB B = 64KB; 3 stages = 192KB
    // conv128 stage = 2*32KB A + 16KB B = 80KB; 2 stages = 160KB
    const int SMEM256 = 3 * (2 * 16384 + 32768);
    const int SMEM128 = 2 * (2 * 32768 + 16384);
    cudaFuncSetAttribute(conv3x3_mma<256, 2, 3>,
        cudaFuncAttributeMaxDynamicSharedMemorySize, SMEM256);
    cudaFuncSetAttribute(conv3x3_mma<128, 2, 2>,
        cudaFuncAttributeMaxDynamicSharedMemorySize, SMEM128);

    const size_t O_S1 = 0, O_S2 = 589824, O_H1 = 1179648, O_O1 = 1769472, O_V1 = 2359296;

    dim3 blk(256);
    nchw2nhwc_split<<<dim3(1024, BATCH), blk>>>(x, xh, xl);
    wprep<<<2304, blk>>>(w_s1, wh + O_S1, wl + O_S1, 256);
    wprep<<<2304, blk>>>(w_s2, wh + O_S2, wl + O_S2, 256);
    wprep<<<2304, blk>>>(w_h1, wh + O_H1, wl + O_H1, 256);
    wprep<<<2304, blk>>>(w_o1, wh + O_O1, wl + O_O1, 256);
    wprep<<<1152, blk>>>(w_v1, wh + O_V1, wl + O_V1, 128);

    dim3 cblk(512);
    dim3 g256(32, BATCH);   // M=128 pixel tiles
    dim3 g128(16, BATCH);   // M=256 pixel tiles

    // stem: 2-pass (exact activations x fp16 weights)
    conv3x3_mma<256, 2, 3><<<g256, cblk, SMEM256>>>(xh, xl, wh + O_S1, wl + O_S1, g_s1, b_s1, ah, al);
    conv3x3_mma<256, 2, 3><<<g256, cblk, SMEM256>>>(ah, al, wh + O_S2, wl + O_S2, g_s2, b_s2, sh, sl);

    // heatmap head
    conv3x3_mma<256, 2, 3><<<g256, cblk, SMEM256>>>(sh, sl, wh + O_H1, wl + O_H1, g_h1, b_h1, th, tl);
    conv1x1_k<256, 17, 4, false><<<128, blk>>>(th, tl, w_h2, c_h2, heat);

    // offset head
    conv3x3_mma<256, 2, 3><<<g256, cblk, SMEM256>>>(sh, sl, wh + O_O1, wl + O_O1, g_o1, b_o1, th, tl);
    conv1x1_k<256, 34, 2, false><<<256, blk>>>(th, tl, w_o2, c_o2, offp);

    // variance head
    conv3x3_mma<128, 2, 2><<<g128, cblk, SMEM128>>>(sh, sl, wh + O_V1, wl + O_V1, g_v1, b_v1, th, tl);
    conv1x1_k<128, 17, 4, true><<<128, blk>>>(th, tl, w_v2, c_v2, varp);

    // fused soft-argmax + refine + offset sampling
    postproc_k<<<BATCH * KPTS, blk>>>(heat, offp, alpha, fusion, fwp, coords, scores);
}

// round 12
// speedup vs baseline: 2.4823x; 1.0078x over previous
#include <cuda_runtime.h>
#include <cuda_fp16.h>
#include <math.h>

#define CIN   256
#define HH    64
#define WW    64
#define NPIX  4096
#define BATCH 32
#define KPTS  17

typedef unsigned short ushort_t;
typedef unsigned int   uint_t;

// ---------------------------------------------------------------------------
// Scratch (device globals — no runtime allocation allowed)
// Activations NHWC fp16 hi/lo: addr = (n*4096 + p)*C + ci
// ---------------------------------------------------------------------------
__device__ __align__(1024) ushort_t g_xh[33554432];
__device__ __align__(1024) ushort_t g_xl[33554432];
__device__ __align__(1024) ushort_t g_ah[33554432];
__device__ __align__(1024) ushort_t g_al[33554432];
__device__ __align__(1024) ushort_t g_sh[33554432];
__device__ __align__(1024) ushort_t g_sl[33554432];
__device__ __align__(1024) ushort_t g_th[33554432];
__device__ __align__(1024) ushort_t g_tl[33554432];
__device__ __align__(1024) ushort_t g_wh[2654208];
__device__ __align__(1024) ushort_t g_wl[2654208];

// ---------------------------------------------------------------------------
__device__ __forceinline__ unsigned smem_to_u32(const void* p) {
    unsigned a;
    asm("{ .reg .u64 t; cvta.to.shared.u64 t, %1; cvt.u32.u64 %0, t; }"
        : "=r"(a) : "l"(p));
    return a;
}
__device__ __forceinline__ ushort_t f2h(float v) {
    __half h = __float2half_rn(v);
    return *(ushort_t*)&h;
}
__device__ __forceinline__ float h2f(ushort_t u) {
    __half h = *(__half*)&u;
    return __half2float(h);
}
__device__ __forceinline__ void ldmatrix_x4(uint_t* r, unsigned addr) {
    asm volatile("ldmatrix.sync.aligned.m8n8.x4.shared.b16 {%0,%1,%2,%3}, [%4];"
                 : "=r"(r[0]), "=r"(r[1]), "=r"(r[2]), "=r"(r[3]) : "r"(addr));
}
__device__ __forceinline__ void mma16816(float* c, const uint_t* a, const uint_t* b) {
    asm volatile(
        "mma.sync.aligned.m16n8k16.row.col.f32.f16.f16.f32 "
        "{%0,%1,%2,%3}, {%4,%5,%6,%7}, {%8,%9}, {%0,%1,%2,%3};"
        : "+f"(c[0]), "+f"(c[1]), "+f"(c[2]), "+f"(c[3])
        : "r"(a[0]), "r"(a[1]), "r"(a[2]), "r"(a[3]), "r"(b[0]), "r"(b[1]));
}
__device__ __forceinline__ void cp16(unsigned dst, const void* src, unsigned sz) {
    asm volatile("cp.async.cg.shared.global [%0], [%1], 16, %2;"
                 :: "r"(dst), "l"(src), "r"(sz) : "memory");
}
__device__ __forceinline__ void cp_commit() {
    asm volatile("cp.async.commit_group;" ::: "memory");
}

// ---------------------------------------------------------------------------
// NCHW fp32 -> NHWC fp16 hi/lo split (tiled 32x32 transpose)
// ---------------------------------------------------------------------------
__global__ __launch_bounds__(256) void nchw2nhwc_split(
    const float* __restrict__ x, ushort_t* __restrict__ h,
    ushort_t* __restrict__ l)
{
    __shared__ float t[32][33];
    const int n  = blockIdx.y;
    const int cb = blockIdx.x >> 7;
    const int pb = blockIdx.x & 127;
    const int lane = threadIdx.x & 31, wr = threadIdx.x >> 5;

    const float* src = x + ((size_t)n * 256 + cb * 32) * 4096 + pb * 32;
#pragma unroll
    for (int j = 0; j < 4; j++) {
        const int ci = wr * 4 + j;
        t[ci][lane] = src[(size_t)ci * 4096 + lane];
    }
    __syncthreads();
#pragma unroll
    for (int j = 0; j < 4; j++) {
        const int p = wr * 4 + j;
        const float v = t[lane][p];
        const ushort_t hb = f2h(v);
        const size_t o = ((size_t)n * 4096 + pb * 32 + p) * 256 + cb * 32 + lane;
        h[o] = hb;
        l[o] = f2h(v - h2f(hb));
    }
}

// ---------------------------------------------------------------------------
// Weight prep: reorder w[co][ci][ky][kx] into 36 chunk-tiles (cc = cb*9 + s),
// each [co][64 ci] K-major with SW128 swizzle baked in, fp16 hi/lo split.
// ---------------------------------------------------------------------------
__global__ __launch_bounds__(256) void wprep(
    const float* __restrict__ w, ushort_t* __restrict__ wh,
    ushort_t* __restrict__ wl, int CO)
{
    int idx = blockIdx.x * 256 + threadIdx.x;
    int co = idx / 2304, r = idx % 2304;
    int ci = r / 9, s = r % 9;
    int cb = ci >> 6, cii = ci & 63;
    int cc = cb * 9 + s;
    unsigned off = (unsigned)(co * 128 + cii * 2) ^ (unsigned)((co & 7) << 4);
    size_t dst = (size_t)cc * CO * 64 + (off >> 1);
    float v = w[idx];
    ushort_t hb = f2h(v);
    wh[dst] = hb;
    wl[dst] = f2h(v - h2f(hb));
}

// ---------------------------------------------------------------------------
// 3x3 SAME conv + BN + ReLU, fp16 hi/lo split mma.sync, NHWC, cp.async pipe.
// PASSES=2: AhBh + AlBh (exact activations x fp16-rounded weights).
// 256 threads (8 warps), warp tile 64x64. COUT=256: M=128 (WM=2, 4 N-warps);
// COUT=128: M=256 (WM=4, 2 N-warps). STAGES=3 where smem allows.
// ---------------------------------------------------------------------------
template <int COUT, int PASSES, int STAGES>
__global__ __launch_bounds__(256, 1) void conv3x3_mma(
    const ushort_t* __restrict__ inh, const ushort_t* __restrict__ inl,
    const ushort_t* __restrict__ wh,  const ushort_t* __restrict__ wl,
    const float* __restrict__ gma, const float* __restrict__ bta,
    ushort_t* __restrict__ outh, ushort_t* __restrict__ outl)
{
    constexpr int MPIX   = (COUT == 256) ? 128 : 256;
    constexpr int ROWS   = MPIX / 64;
    constexpr int WM     = MPIX / 64;           // warps along M (warp tile M=64)
    constexpr int ABYTES = MPIX * 128;
    constexpr int BBYTES = COUT * 128;
    constexpr int BPL    = (PASSES == 3) ? 2 : 1;
    constexpr int STAGE  = 2 * ABYTES + BPL * BBYTES;

    extern __shared__ __align__(1024) char smem[];
    const unsigned sb = smem_to_u32(smem);
    const int tid = threadIdx.x, wid = tid >> 5, lane = tid & 31;
    const int n = blockIdx.y, r0 = blockIdx.x * ROWS;

    const int warp_m = wid % WM;     // 64 pixels each
    const int warp_n = wid / WM;     // 64 couts each

    float acc[4][8][4];
#pragma unroll
    for (int mt = 0; mt < 4; mt++)
#pragma unroll
        for (int nt = 0; nt < 8; nt++)
#pragma unroll
            for (int c = 0; c < 4; c++) acc[mt][nt][c] = 0.f;

    auto issue = [&](int cc, int st) {
        const int cb = cc / 9, s = cc - cb * 9;
        const int ky = s / 3, kx = s - ky * 3;
        const unsigned sbase = sb + st * STAGE;
#pragma unroll
        for (int i = tid; i < MPIX * 16; i += 256) {
            const int plane = i / (MPIX * 8);
            const int r = i - plane * (MPIX * 8);
            const int px = r >> 3, g = r & 7;
            const int row = r0 + (px >> 6) + ky - 1;
            const int col = (px & 63) + kx - 1;
            const bool ok = (row >= 0) && (row < HH) && (col >= 0) && (col < WW);
            const ushort_t* src = (plane ? inl : inh)
                + ((size_t)(n * 4096 + (ok ? row * 64 + col : 0))) * 256
                + cb * 64 + g * 8;
            const unsigned dst = sbase + plane * ABYTES
                + (((unsigned)(px * 128 + g * 16)) ^ ((unsigned)((px & 7) << 4)));
            cp16(dst, src, ok ? 16u : 0u);
        }
#pragma unroll
        for (int i = tid; i < COUT * 8 * BPL; i += 256) {
            const int plane = i / (COUT * 8);
            const int r = i - plane * (COUT * 8);
            const ushort_t* src = (plane ? wl : wh) + (size_t)cc * COUT * 64 + r * 8;
            const unsigned dst = sbase + 2 * ABYTES + plane * BBYTES + r * 16;
            cp16(dst, src, 16);
        }
        cp_commit();
    };

    auto compute = [&](unsigned ab) {
        const unsigned bb = ab + 2 * ABYTES;
#pragma unroll
        for (int k4 = 0; k4 < 4; k4++) {
            const unsigned kb = (unsigned)(k4 * 32);
            uint_t Bh[8][2], Bl[8][2];
            {
                const int j = lane & 7, g = lane >> 3;
                const int ntp = g >> 1, kh = g & 1;
#pragma unroll
                for (int q = 0; q < 4; q++) {
                    const unsigned row = (unsigned)(warp_n * 64 + (q * 2 + ntp) * 8 + j);
                    const unsigned off = (row * 128 + kb + (unsigned)(kh * 16))
                                         ^ ((unsigned)j << 4);
                    uint_t r[4];
                    ldmatrix_x4(r, bb + off);
                    Bh[q*2][0] = r[0]; Bh[q*2][1] = r[1];
                    Bh[q*2+1][0] = r[2]; Bh[q*2+1][1] = r[3];
                    if (PASSES == 3) {
                        ldmatrix_x4(r, bb + BBYTES + off);
                        Bl[q*2][0] = r[0]; Bl[q*2][1] = r[1];
                        Bl[q*2+1][0] = r[2]; Bl[q*2+1][1] = r[3];
                    }
                }
            }
#pragma unroll
            for (int mt = 0; mt < 4; mt++) {
                const unsigned arow = (unsigned)(warp_m * 64 + mt * 16 + (lane & 15));
                const unsigned off = (arow * 128 + kb + (unsigned)((lane >> 4) << 4))
                                     ^ ((arow & 7) << 4);
                uint_t A[4];
                ldmatrix_x4(A, ab + off);                 // Ah
#pragma unroll
                for (int nt = 0; nt < 8; nt++) {
                    mma16816(acc[mt][nt], A, Bh[nt]);     // Ah*Bh
                    if (PASSES == 3)
                        mma16816(acc[mt][nt], A, Bl[nt]); // Ah*Bl
                }
            }
#pragma unroll
            for (int mt = 0; mt < 4; mt++) {
                const unsigned arow = (unsigned)(warp_m * 64 + mt * 16 + (lane & 15));
                const unsigned off = (arow * 128 + kb + (unsigned)((lane >> 4) << 4))
                                     ^ ((arow & 7) << 4);
                uint_t A[4];
                ldmatrix_x4(A, ab + ABYTES + off);        // Al
#pragma unroll
                for (int nt = 0; nt < 8; nt++)
                    mma16816(acc[mt][nt], A, Bh[nt]);     // Al*Bh
            }
        }
    };

    if (STAGES == 3) {
        // 3-stage pipeline: one barrier per chunk, two fills in flight.
        issue(0, 0);
        issue(1, 1);
        int st = 0;
        for (int cc = 0; cc < 36; cc++) {
            if (cc < 35)
                asm volatile("cp.async.wait_group 1;" ::: "memory");
            else
                asm volatile("cp.async.wait_group 0;" ::: "memory");
            __syncthreads();
            if (cc + 2 < 36) {
                int st2 = st + 2; if (st2 >= 3) st2 -= 3;
                issue(cc + 2, st2);
            }
            compute(sb + st * STAGE);
            if (++st == 3) st = 0;
        }
    } else {
        // 2-stage double buffer (used when 3 stages exceed smem).
        issue(0, 0);
        for (int cc = 0; cc < 36; cc++) {
            const int cur = cc & 1;
            if (cc < 35) {
                issue(cc + 1, cur ^ 1);
                asm volatile("cp.async.wait_group 1;" ::: "memory");
            } else {
                asm volatile("cp.async.wait_group 0;" ::: "memory");
            }
            __syncthreads();
            compute(sb + cur * STAGE);
            __syncthreads();
        }
    }

    // ---- epilogue: BN + ReLU + fp16 hi/lo split, NHWC packed u32 stores ----
    const float rs = rsqrtf(1.0f + 1e-5f);
    float sc[8][2], bs[8][2];
#pragma unroll
    for (int nt = 0; nt < 8; nt++)
#pragma unroll
        for (int j = 0; j < 2; j++) {
            const int co = warp_n * 64 + nt * 8 + (lane & 3) * 2 + j;
            sc[nt][j] = gma[co] * rs;
            bs[nt][j] = bta[co];
        }

#pragma unroll
    for (int mt = 0; mt < 4; mt++)
#pragma unroll
        for (int ch = 0; ch < 2; ch++) {
            const int p = warp_m * 64 + mt * 16 + (lane >> 2) + ch * 8;
            const size_t base = ((size_t)n * 4096 + r0 * 64 + p) * COUT
                              + warp_n * 64 + (lane & 3) * 2;
#pragma unroll
            for (int nt = 0; nt < 8; nt++) {
                const float v0 = fmaxf(fmaf(acc[mt][nt][ch*2+0], sc[nt][0], bs[nt][0]), 0.f);
                const float v1 = fmaxf(fmaf(acc[mt][nt][ch*2+1], sc[nt][1], bs[nt][1]), 0.f);
                const ushort_t h0 = f2h(v0), h1 = f2h(v1);
                const uint_t ph = (uint_t)h0 | ((uint_t)h1 << 16);
                const uint_t pl = (uint_t)f2h(v0 - h2f(h0))
                                | ((uint_t)f2h(v1 - h2f(h1)) << 16);
                *(uint_t*)(outh + base + nt * 8) = ph;
                *(uint_t*)(outl + base + nt * 8) = pl;
            }
        }
}

// ---------------------------------------------------------------------------
// 1x1 conv head from NHWC fp16 hi/lo; fp32 weights/accum; NCHW fp32 out.
// PPT pixels per thread: each broadcast-LDS weight feeds PPT FMAs.
// ---------------------------------------------------------------------------
template <int CI, int CO, int PPT, bool SOFTPLUS>
__global__ __launch_bounds__(256) void conv1x1_k(
    const ushort_t* __restrict__ inh, const ushort_t* __restrict__ inl,
    const float* __restrict__ w, const float* __restrict__ bias,
    float* __restrict__ out)
{
    __shared__ float s_w[CI * CO];   // [ci][co]
    const int tid = threadIdx.x;
    for (int i = tid; i < CI * CO; i += 256)
        s_w[(i % CI) * CO + i / CI] = w[i];
    __syncthreads();

    const int pid0 = (blockIdx.x * 256 + tid) * PPT;
    const int n = pid0 >> 12;

    float acc[PPT][CO];
#pragma unroll
    for (int q = 0; q < PPT; q++)
#pragma unroll
        for (int c = 0; c < CO; c++) acc[q][c] = 0.f;

    for (int u = 0; u < CI / 8; u++) {
        float v[PPT][8];
#pragma unroll
        for (int q = 0; q < PPT; q++) {
            const uint4 qh = *(const uint4*)(inh + (size_t)(pid0 + q) * CI + u * 8);
            const uint4 ql = *(const uint4*)(inl + (size_t)(pid0 + q) * CI + u * 8);
            const uint_t hw[4] = {qh.x, qh.y, qh.z, qh.w};
            const uint_t lw[4] = {ql.x, ql.y, ql.z, ql.w};
#pragma unroll
            for (int g = 0; g < 4; g++) {
                v[q][g*2+0] = h2f((ushort_t)hw[g]) + h2f((ushort_t)lw[g]);
                v[q][g*2+1] = h2f((ushort_t)(hw[g] >> 16)) + h2f((ushort_t)(lw[g] >> 16));
            }
        }
#pragma unroll
        for (int g = 0; g < 8; g++) {
            const int ci = u * 8 + g;
#pragma unroll
            for (int co = 0; co < CO; co++) {
                const float wv = s_w[ci * CO + co];
#pragma unroll
                for (int q = 0; q < PPT; q++)
                    acc[q][co] = fmaf(v[q][g], wv, acc[q][co]);
            }
        }
    }
#pragma unroll
    for (int q = 0; q < PPT; q++) {
        const int p = (pid0 + q) & 4095;
#pragma unroll
        for (int co = 0; co < CO; co++) {
            float o = acc[q][co] + bias[co];
            if (SOFTPLUS)
                o = (o > 0.f) ? (o + log1pf(expf(-o))) : log1pf(expf(o));
            out[((size_t)n * CO + co) * NPIX + p] = o;
        }
    }
}

// ---------------------------------------------------------------------------
// Fused postprocessing (reads NCHW heat/off)
// ---------------------------------------------------------------------------
__global__ __launch_bounds__(256) void postproc_k(
    const float* __restrict__ heat, const float* __restrict__ off,
    const float* __restrict__ alpha_p, const float* __restrict__ fusion_p,
    float* __restrict__ fw_out, float* __restrict__ coords_out,
    float* __restrict__ scores_out)
{
    __shared__ float r0[256], r1[256], r2[256];
    const int bk  = blockIdx.x;
    const int tid = threadIdx.x;
    const float* hm = heat + (size_t)bk * NPIX;

    float lm = -1e30f;
#pragma unroll
    for (int i = 0; i < 16; i++) lm = fmaxf(lm, hm[tid + i * 256]);
    r0[tid] = lm;
    __syncthreads();
    for (int s = 128; s > 0; s >>= 1) {
        if (tid < s) r0[tid] = fmaxf(r0[tid], r0[tid + s]);
        __syncthreads();
    }
    const float m = r0[0];
    __syncthreads();

    float se = 0.f, sx = 0.f, sy = 0.f;
#pragma unroll
    for (int i = 0; i < 16; i++) {
        const int idx = tid + i * 256;
        const float e = expf(hm[idx] - m);
        se += e;
        sx += e * (float)(idx & 63);
        sy += e * (float)(idx >> 6);
    }
    r0[tid] = se; r1[tid] = sx; r2[tid] = sy;
    __syncthreads();
    for (int s = 128; s > 0; s >>= 1) {
        if (tid < s) {
            r0[tid] += r0[tid + s];
            r1[tid] += r1[tid + s];
            r2[tid] += r2[tid + s];
        }
        __syncthreads();
    }

    if (tid == 0) {
        const float inv = 1.f / r0[0];
        const float xc = r1[0] * inv;
        const float yc = r2[0] * inv;

        const int px = (int)rintf(fminf(fmaxf(xc, 0.f), 63.f));
        const int py = (int)rintf(fminf(fmaxf(yc, 0.f), 63.f));
        int pxs[5], pys[5]; bool okx[5], oky[5];
#pragma unroll
        for (int i = 0; i < 5; i++) {
            const int xs = px - 2 + i; okx[i] = (xs >= 0 && xs < WW); pxs[i] = min(max(xs, 0), 63);
            const int ys = py - 2 + i; oky[i] = (ys >= 0 && ys < HH); pys[i] = min(max(ys, 0), 63);
        }
        float pv[25];
        float pm = -1e30f;
        for (int j = 0; j < 5; j++)
            for (int i = 0; i < 5; i++) {
                const float v = hm[pys[j] * WW + pxs[i]];
                pv[j * 5 + i] = v;
                if (okx[i] && oky[j]) pm = fmaxf(pm, v);
            }
        float ws = 0.f, rx = 0.f, ry = 0.f;
        for (int j = 0; j < 5; j++)
            for (int i = 0; i < 5; i++)
                if (okx[i] && oky[j]) {
                    const float e = expf(pv[j * 5 + i] - pm);
                    ws += e;
                    rx += e * (float)pxs[i];
                    ry += e * (float)pys[j];
                }
        rx /= ws; ry /= ws;

        const float a   = 1.f / (1.f + expf(-alpha_p[0]));
        const float fwv = 1.f / (1.f + expf(-fusion_p[0]));
        float cx = a * xc + (1.f - a) * rx;
        float cy = a * yc + (1.f - a) * ry;

        const float ix = fminf(fmaxf(cx, 0.f), 63.f);
        const float iy = fminf(fmaxf(cy, 0.f), 63.f);
        const float x0f = floorf(ix), y0f = floorf(iy);
        const float wx = ix - x0f, wy = iy - y0f;
        const int x0 = min(max((int)x0f, 0), 63);
        const int y0 = min(max((int)y0f, 0), 63);
        const int x1 = min(x0 + 1, 63);
        const int y1 = min(y0 + 1, 63);
        const float* ob = off + (size_t)bk * 2 * NPIX;
        float sv[2];
#pragma unroll
        for (int ch = 0; ch < 2; ch++) {
            const float* o = ob + ch * NPIX;
            const float v00 = o[y0 * WW + x0], v01 = o[y0 * WW + x1];
            const float v10 = o[y1 * WW + x0], v11 = o[y1 * WW + x1];
            sv[ch] = (1.f - wy) * ((1.f - wx) * v00 + wx * v01)
                   + wy * ((1.f - wx) * v10 + wx * v11);
        }
        cx += fwv * sv[0];
        cy += fwv * sv[1];

        coords_out[bk * 2 + 0] = cx;
        coords_out[bk * 2 + 1] = cy;
        scores_out[bk] = m;
        if (bk == 0) fw_out[0] = fwv;
    }
}

// ---------------------------------------------------------------------------
extern "C" void kernel_launch(void* const* d_in, const int* in_sizes, int n_in,
                              void* d_out, int out_size)
{
    const float* x    = (const float*)d_in[0];
    const float* w_s1 = (const float*)d_in[1];
    const float* g_s1 = (const float*)d_in[2];
    const float* b_s1 = (const float*)d_in[3];
    const float* w_s2 = (const float*)d_in[4];
    const float* g_s2 = (const float*)d_in[5];
    const float* b_s2 = (const float*)d_in[6];
    const float* w_h1 = (const float*)d_in[7];
    const float* g_h1 = (const float*)d_in[8];
    const float* b_h1 = (const float*)d_in[9];
    const float* w_h2 = (const float*)d_in[10];
    const float* c_h2 = (const float*)d_in[11];
    const float* w_o1 = (const float*)d_in[12];
    const float* g_o1 = (const float*)d_in[13];
    const float* b_o1 = (const float*)d_in[14];
    const float* w_o2 = (const float*)d_in[15];
    const float* c_o2 = (const float*)d_in[16];
    const float* w_v1 = (const float*)d_in[17];
    const float* g_v1 = (const float*)d_in[18];
    const float* b_v1 = (const float*)d_in[19];
    const float* w_v2 = (const float*)d_in[20];
    const float* c_v2 = (const float*)d_in[21];
    const float* alpha  = (const float*)d_in[22];
    const float* fusion = (const float*)d_in[23];

    float* out    = (float*)d_out;
    float* heat   = out;
    float* offp   = out + 2228224;
    float* varp   = out + 6684672;
    float* fwp    = out + 8912896;
    float* coords = out + 8912897;
    float* scores = out + 8913985;

    ushort_t *xh, *xl, *ah, *al, *sh, *sl, *th, *tl, *wh, *wl;
    cudaGetSymbolAddress((void**)&xh, g_xh);
    cudaGetSymbolAddress((void**)&xl, g_xl);
    cudaGetSymbolAddress((void**)&ah, g_ah);
    cudaGetSymbolAddress((void**)&al, g_al);
    cudaGetSymbolAddress((void**)&sh, g_sh);
    cudaGetSymbolAddress((void**)&sl, g_sl);
    cudaGetSymbolAddress((void**)&th, g_th);
    cudaGetSymbolAddress((void**)&tl, g_tl);
    cudaGetSymbolAddress((void**)&wh, g_wh);
    cudaGetSymbolAddress((void**)&wl, g_wl);

    // conv256 stage = 2*16KB A + 32KB B = 64KB; 3 stages = 192KB
    // conv128 stage = 2*32KB A + 16KB B = 80KB; 2 stages = 160KB
    const int SMEM256 = 3 * (2 * 16384 + 32768);
    const int SMEM128 = 2 * (2 * 32768 + 16384);
    cudaFuncSetAttribute(conv3x3_mma<256, 2, 3>,
        cudaFuncAttributeMaxDynamicSharedMemorySize, SMEM256);
    cudaFuncSetAttribute(conv3x3_mma<128, 2, 2>,
        cudaFuncAttributeMaxDynamicSharedMemorySize, SMEM128);

    const size_t O_S1 = 0, O_S2 = 589824, O_H1 = 1179648, O_O1 = 1769472, O_V1 = 2359296;

    dim3 blk(256);
    dim3 cblk(256);
    dim3 g256(32, BATCH);   // M=128 pixel tiles
    dim3 g128(16, BATCH);   // M=256 pixel tiles

    // prep (ordered so launch #6 — the ncu-profiled one — is conv_s1)
    nchw2nhwc_split<<<dim3(1024, BATCH), blk>>>(x, xh, xl);         // 1
    wprep<<<2304, blk>>>(w_s1, wh + O_S1, wl + O_S1, 256);          // 2
    wprep<<<2304, blk>>>(w_s2, wh + O_S2, wl + O_S2, 256);          // 3
    wprep<<<2304, blk>>>(w_h1, wh + O_H1, wl + O_H1, 256);          // 4
    wprep<<<2304, blk>>>(w_o1, wh + O_O1, wl + O_O1, 256);          // 5

    // stem: 2-pass (exact activations x fp16 weights)
    conv3x3_mma<256, 2, 3><<<g256, cblk, SMEM256>>>(xh, xl, wh + O_S1, wl + O_S1, g_s1, b_s1, ah, al);  // 6 (profiled)
    wprep<<<1152, blk>>>(w_v1, wh + O_V1, wl + O_V1, 128);          // 7
    conv3x3_mma<256, 2, 3><<<g256, cblk, SMEM256>>>(ah, al, wh + O_S2, wl + O_S2, g_s2, b_s2, sh, sl);

    // heatmap head
    conv3x3_mma<256, 2, 3><<<g256, cblk, SMEM256>>>(sh, sl, wh + O_H1, wl + O_H1, g_h1, b_h1, th, tl);
    conv1x1_k<256, 17, 4, false><<<128, blk>>>(th, tl, w_h2, c_h2, heat);

    // offset head
    conv3x3_mma<256, 2, 3><<<g256, cblk, SMEM256>>>(sh, sl, wh + O_O1, wl + O_O1, g_o1, b_o1, th, tl);
    conv1x1_k<256, 34, 2, false><<<256, blk>>>(th, tl, w_o2, c_o2, offp);

    // variance head
    conv3x3_mma<128, 2, 2><<<g128, cblk, SMEM128>>>(sh, sl, wh + O_V1, wl + O_V1, g_v1, b_v1, th, tl);
    conv1x1_k<128, 17, 4, true><<<128, blk>>>(th, tl, w_v2, c_v2, varp);

    // fused soft-argmax + refine + offset sampling
    postproc_k<<<BATCH * KPTS, blk>>>(heat, offp, alpha, fusion, fwp, coords, scores);
}

// round 14
// speedup vs baseline: 3.1820x; 1.2819x over previous
#include <cuda_runtime.h>
#include <cuda_fp16.h>
#include <math.h>

#define CIN   256
#define HH    64
#define WW    64
#define NPIX  4096
#define BATCH 32
#define KPTS  17

typedef unsigned short ushort_t;
typedef unsigned int   uint_t;

// ---------------------------------------------------------------------------
// Scratch (device globals — no runtime allocation allowed)
// Activations NHWC fp16 hi/lo: addr = (n*4096 + p)*C + ci
// ---------------------------------------------------------------------------
__device__ __align__(1024) ushort_t g_xh[33554432];
__device__ __align__(1024) ushort_t g_xl[33554432];
__device__ __align__(1024) ushort_t g_ah[33554432];
__device__ __align__(1024) ushort_t g_al[33554432];
__device__ __align__(1024) ushort_t g_sh[33554432];
__device__ __align__(1024) ushort_t g_sl[33554432];
__device__ __align__(1024) ushort_t g_th[33554432];
__device__ __align__(1024) ushort_t g_tl[33554432];
__device__ __align__(1024) ushort_t g_wh[2654208];
__device__ __align__(1024) ushort_t g_wl[2654208];

// ---------------------------------------------------------------------------
__device__ __forceinline__ unsigned smem_to_u32(const void* p) {
    unsigned a;
    asm("{ .reg .u64 t; cvta.to.shared.u64 t, %1; cvt.u32.u64 %0, t; }"
        : "=r"(a) : "l"(p));
    return a;
}
__device__ __forceinline__ ushort_t f2h(float v) {
    __half h = __float2half_rn(v);
    return *(ushort_t*)&h;
}
__device__ __forceinline__ float h2f(ushort_t u) {
    __half h = *(__half*)&u;
    return __half2float(h);
}
__device__ __forceinline__ void ldmatrix_x4(uint_t* r, unsigned addr) {
    asm volatile("ldmatrix.sync.aligned.m8n8.x4.shared.b16 {%0,%1,%2,%3}, [%4];"
                 : "=r"(r[0]), "=r"(r[1]), "=r"(r[2]), "=r"(r[3]) : "r"(addr));
}
__device__ __forceinline__ void mma16816(float* c, const uint_t* a, const uint_t* b) {
    asm volatile(
        "mma.sync.aligned.m16n8k16.row.col.f32.f16.f16.f32 "
        "{%0,%1,%2,%3}, {%4,%5,%6,%7}, {%8,%9}, {%0,%1,%2,%3};"
        : "+f"(c[0]), "+f"(c[1]), "+f"(c[2]), "+f"(c[3])
        : "r"(a[0]), "r"(a[1]), "r"(a[2]), "r"(a[3]), "r"(b[0]), "r"(b[1]));
}
__device__ __forceinline__ void cp16(unsigned dst, const void* src, unsigned sz) {
    asm volatile("cp.async.cg.shared.global [%0], [%1], 16, %2;"
                 :: "r"(dst), "l"(src), "r"(sz) : "memory");
}
__device__ __forceinline__ void cp_commit() {
    asm volatile("cp.async.commit_group;" ::: "memory");
}

// ---------------------------------------------------------------------------
// NCHW fp32 -> NHWC fp16 hi/lo split (tiled 32x32 transpose)
// ---------------------------------------------------------------------------
__global__ __launch_bounds__(256) void nchw2nhwc_split(
    const float* __restrict__ x, ushort_t* __restrict__ h,
    ushort_t* __restrict__ l)
{
    __shared__ float t[32][33];
    const int n  = blockIdx.y;
    const int cb = blockIdx.x >> 7;
    const int pb = blockIdx.x & 127;
    const int lane = threadIdx.x & 31, wr = threadIdx.x >> 5;

    const float* src = x + ((size_t)n * 256 + cb * 32) * 4096 + pb * 32;
#pragma unroll
    for (int j = 0; j < 4; j++) {
        const int ci = wr * 4 + j;
        t[ci][lane] = src[(size_t)ci * 4096 + lane];
    }
    __syncthreads();
#pragma unroll
    for (int j = 0; j < 4; j++) {
        const int p = wr * 4 + j;
        const float v = t[lane][p];
        const ushort_t hb = f2h(v);
        const size_t o = ((size_t)n * 4096 + pb * 32 + p) * 256 + cb * 32 + lane;
        h[o] = hb;
        l[o] = f2h(v - h2f(hb));
    }
}

// ---------------------------------------------------------------------------
// Weight prep: reorder w[co][ci][ky][kx] into 36 chunk-tiles (cc = cb*9 + s),
// each [co][64 ci] K-major with SW128 swizzle baked in, fp16 hi/lo split.
// ---------------------------------------------------------------------------
__global__ __launch_bounds__(256) void wprep(
    const float* __restrict__ w, ushort_t* __restrict__ wh,
    ushort_t* __restrict__ wl, int CO)
{
    int idx = blockIdx.x * 256 + threadIdx.x;
    int co = idx / 2304, r = idx % 2304;
    int ci = r / 9, s = r % 9;
    int cb = ci >> 6, cii = ci & 63;
    int cc = cb * 9 + s;
    unsigned off = (unsigned)(co * 128 + cii * 2) ^ (unsigned)((co & 7) << 4);
    size_t dst = (size_t)cc * CO * 64 + (off >> 1);
    float v = w[idx];
    ushort_t hb = f2h(v);
    wh[dst] = hb;
    wl[dst] = f2h(v - h2f(hb));
}

// ---------------------------------------------------------------------------
// 3x3 SAME conv + BN + ReLU, fp16 split mma.sync, NHWC, cp.async pipe.
// PASSES=2: AhBh + AlBh (exact activations x fp16 weights, err ~2.7e-4)
// PASSES=1: AhBh only    (fp16 activations  x fp16 weights, err ~2x that)
// 256 threads (8 warps), warp tile 64x64. COUT=256: M=128; COUT=128: M=256.
// STAGES=3: one barrier per chunk, two stage-fills in flight.
// ---------------------------------------------------------------------------
template <int COUT, int PASSES, int STAGES>
__global__ __launch_bounds__(256, 1) void conv3x3_mma(
    const ushort_t* __restrict__ inh, const ushort_t* __restrict__ inl,
    const ushort_t* __restrict__ wh,  const ushort_t* __restrict__ wl,
    const float* __restrict__ gma, const float* __restrict__ bta,
    ushort_t* __restrict__ outh, ushort_t* __restrict__ outl)
{
    constexpr int MPIX   = (COUT == 256) ? 128 : 256;
    constexpr int ROWS   = MPIX / 64;
    constexpr int WM     = MPIX / 64;           // warps along M (warp tile M=64)
    constexpr int ABYTES = MPIX * 128;
    constexpr int BBYTES = COUT * 128;
    constexpr int APL    = (PASSES >= 2) ? 2 : 1;   // A planes staged
    constexpr int BPL    = (PASSES == 3) ? 2 : 1;   // B planes staged
    constexpr int STAGE  = APL * ABYTES + BPL * BBYTES;

    extern __shared__ __align__(1024) char smem[];
    const unsigned sb = smem_to_u32(smem);
    const int tid = threadIdx.x, wid = tid >> 5, lane = tid & 31;
    const int n = blockIdx.y, r0 = blockIdx.x * ROWS;

    const int warp_m = wid % WM;     // 64 pixels each
    const int warp_n = wid / WM;     // 64 couts each

    float acc[4][8][4];
#pragma unroll
    for (int mt = 0; mt < 4; mt++)
#pragma unroll
        for (int nt = 0; nt < 8; nt++)
#pragma unroll
            for (int c = 0; c < 4; c++) acc[mt][nt][c] = 0.f;

    auto issue = [&](int cc, int st) {
        const int cb = cc / 9, s = cc - cb * 9;
        const int ky = s / 3, kx = s - ky * 3;
        const unsigned sbase = sb + st * STAGE;
#pragma unroll
        for (int i = tid; i < MPIX * 8 * APL; i += 256) {
            const int plane = i / (MPIX * 8);
            const int r = i - plane * (MPIX * 8);
            const int px = r >> 3, g = r & 7;
            const int row = r0 + (px >> 6) + ky - 1;
            const int col = (px & 63) + kx - 1;
            const bool ok = (row >= 0) && (row < HH) && (col >= 0) && (col < WW);
            const ushort_t* src = (plane ? inl : inh)
                + ((size_t)(n * 4096 + (ok ? row * 64 + col : 0))) * 256
                + cb * 64 + g * 8;
            const unsigned dst = sbase + plane * ABYTES
                + (((unsigned)(px * 128 + g * 16)) ^ ((unsigned)((px & 7) << 4)));
            cp16(dst, src, ok ? 16u : 0u);
        }
#pragma unroll
        for (int i = tid; i < COUT * 8 * BPL; i += 256) {
            const int plane = i / (COUT * 8);
            const int r = i - plane * (COUT * 8);
            const ushort_t* src = (plane ? wl : wh) + (size_t)cc * COUT * 64 + r * 8;
            const unsigned dst = sbase + APL * ABYTES + plane * BBYTES + r * 16;
            cp16(dst, src, 16);
        }
        cp_commit();
    };

    auto compute = [&](unsigned ab) {
        const unsigned bb = ab + APL * ABYTES;
#pragma unroll
        for (int k4 = 0; k4 < 4; k4++) {
            const unsigned kb = (unsigned)(k4 * 32);
            uint_t Bh[8][2], Bl[8][2];
            {
                const int j = lane & 7, g = lane >> 3;
                const int ntp = g >> 1, kh = g & 1;
#pragma unroll
                for (int q = 0; q < 4; q++) {
                    const unsigned row = (unsigned)(warp_n * 64 + (q * 2 + ntp) * 8 + j);
                    const unsigned off = (row * 128 + kb + (unsigned)(kh * 16))
                                         ^ ((unsigned)j << 4);
                    uint_t r[4];
                    ldmatrix_x4(r, bb + off);
                    Bh[q*2][0] = r[0]; Bh[q*2][1] = r[1];
                    Bh[q*2+1][0] = r[2]; Bh[q*2+1][1] = r[3];
                    if (PASSES == 3) {
                        ldmatrix_x4(r, bb + BBYTES + off);
                        Bl[q*2][0] = r[0]; Bl[q*2][1] = r[1];
                        Bl[q*2+1][0] = r[2]; Bl[q*2+1][1] = r[3];
                    }
                }
            }
#pragma unroll
            for (int mt = 0; mt < 4; mt++) {
                const unsigned arow = (unsigned)(warp_m * 64 + mt * 16 + (lane & 15));
                const unsigned off = (arow * 128 + kb + (unsigned)((lane >> 4) << 4))
                                     ^ ((arow & 7) << 4);
                uint_t A[4];
                ldmatrix_x4(A, ab + off);                 // Ah
#pragma unroll
                for (int nt = 0; nt < 8; nt++) {
                    mma16816(acc[mt][nt], A, Bh[nt]);     // Ah*Bh
                    if (PASSES == 3)
                        mma16816(acc[mt][nt], A, Bl[nt]); // Ah*Bl
                }
            }
            if (PASSES >= 2) {
#pragma unroll
                for (int mt = 0; mt < 4; mt++) {
                    const unsigned arow = (unsigned)(warp_m * 64 + mt * 16 + (lane & 15));
                    const unsigned off = (arow * 128 + kb + (unsigned)((lane >> 4) << 4))
                                         ^ ((arow & 7) << 4);
                    uint_t A[4];
                    ldmatrix_x4(A, ab + ABYTES + off);    // Al
#pragma unroll
                    for (int nt = 0; nt < 8; nt++)
                        mma16816(acc[mt][nt], A, Bh[nt]); // Al*Bh
                }
            }
        }
    };

    if (STAGES == 3) {
        // 3-stage pipeline: one barrier per chunk, two fills in flight.
        issue(0, 0);
        issue(1, 1);
        int st = 0;
        for (int cc = 0; cc < 36; cc++) {
            if (cc < 35)
                asm volatile("cp.async.wait_group 1;" ::: "memory");
            else
                asm volatile("cp.async.wait_group 0;" ::: "memory");
            __syncthreads();
            if (cc + 2 < 36) {
                int st2 = st + 2; if (st2 >= 3) st2 -= 3;
                issue(cc + 2, st2);
            }
            compute(sb + st * STAGE);
            if (++st == 3) st = 0;
        }
    } else {
        // 2-stage double buffer (fallback when 3 stages exceed smem).
        issue(0, 0);
        for (int cc = 0; cc < 36; cc++) {
            const int cur = cc & 1;
            if (cc < 35) {
                issue(cc + 1, cur ^ 1);
                asm volatile("cp.async.wait_group 1;" ::: "memory");
            } else {
                asm volatile("cp.async.wait_group 0;" ::: "memory");
            }
            __syncthreads();
            compute(sb + cur * STAGE);
            __syncthreads();
        }
    }

    // ---- epilogue: BN + ReLU + fp16 hi/lo split, NHWC packed u32 stores ----
    const float rs = rsqrtf(1.0f + 1e-5f);
    float sc[8][2], bs[8][2];
#pragma unroll
    for (int nt = 0; nt < 8; nt++)
#pragma unroll
        for (int j = 0; j < 2; j++) {
            const int co = warp_n * 64 + nt * 8 + (lane & 3) * 2 + j;
            sc[nt][j] = gma[co] * rs;
            bs[nt][j] = bta[co];
        }

#pragma unroll
    for (int mt = 0; mt < 4; mt++)
#pragma unroll
        for (int ch = 0; ch < 2; ch++) {
            const int p = warp_m * 64 + mt * 16 + (lane >> 2) + ch * 8;
            const size_t base = ((size_t)n * 4096 + r0 * 64 + p) * COUT
                              + warp_n * 64 + (lane & 3) * 2;
#pragma unroll
            for (int nt = 0; nt < 8; nt++) {
                const float v0 = fmaxf(fmaf(acc[mt][nt][ch*2+0], sc[nt][0], bs[nt][0]), 0.f);
                const float v1 = fmaxf(fmaf(acc[mt][nt][ch*2+1], sc[nt][1], bs[nt][1]), 0.f);
                const ushort_t h0 = f2h(v0), h1 = f2h(v1);
                const uint_t ph = (uint_t)h0 | ((uint_t)h1 << 16);
                const uint_t pl = (uint_t)f2h(v0 - h2f(h0))
                                | ((uint_t)f2h(v1 - h2f(h1)) << 16);
                *(uint_t*)(outh + base + nt * 8) = ph;
                *(uint_t*)(outl + base + nt * 8) = pl;
            }
        }
}

// ---------------------------------------------------------------------------
// 1x1 conv head from NHWC fp16 hi/lo; fp32 weights/accum; NCHW fp32 out.
// PPT pixels per thread: each broadcast-LDS weight feeds PPT FMAs.
// ---------------------------------------------------------------------------
template <int CI, int CO, int PPT, bool SOFTPLUS>
__global__ __launch_bounds__(256) void conv1x1_k(
    const ushort_t* __restrict__ inh, const ushort_t* __restrict__ inl,
    const float* __restrict__ w, const float* __restrict__ bias,
    float* __restrict__ out)
{
    __shared__ float s_w[CI * CO];   // [ci][co]
    const int tid = threadIdx.x;
    for (int i = tid; i < CI * CO; i += 256)
        s_w[(i % CI) * CO + i / CI] = w[i];
    __syncthreads();

    const int pid0 = (blockIdx.x * 256 + tid) * PPT;
    const int n = pid0 >> 12;

    float acc[PPT][CO];
#pragma unroll
    for (int q = 0; q < PPT; q++)
#pragma unroll
        for (int c = 0; c < CO; c++) acc[q][c] = 0.f;

    for (int u = 0; u < CI / 8; u++) {
        float v[PPT][8];
#pragma unroll
        for (int q = 0; q < PPT; q++) {
            const uint4 qh = *(const uint4*)(inh + (size_t)(pid0 + q) * CI + u * 8);
            const uint4 ql = *(const uint4*)(inl + (size_t)(pid0 + q) * CI + u * 8);
            const uint_t hw[4] = {qh.x, qh.y, qh.z, qh.w};
            const uint_t lw[4] = {ql.x, ql.y, ql.z, ql.w};
#pragma unroll
            for (int g = 0; g < 4; g++) {
                v[q][g*2+0] = h2f((ushort_t)hw[g]) + h2f((ushort_t)lw[g]);
                v[q][g*2+1] = h2f((ushort_t)(hw[g] >> 16)) + h2f((ushort_t)(lw[g] >> 16));
            }
        }
#pragma unroll
        for (int g = 0; g < 8; g++) {
            const int ci = u * 8 + g;
#pragma unroll
            for (int co = 0; co < CO; co++) {
                const float wv = s_w[ci * CO + co];
#pragma unroll
                for (int q = 0; q < PPT; q++)
                    acc[q][co] = fmaf(v[q][g], wv, acc[q][co]);
            }
        }
    }
#pragma unroll
    for (int q = 0; q < PPT; q++) {
        const int p = (pid0 + q) & 4095;
#pragma unroll
        for (int co = 0; co < CO; co++) {
            float o = acc[q][co] + bias[co];
            if (SOFTPLUS)
                o = (o > 0.f) ? (o + log1pf(expf(-o))) : log1pf(expf(o));
            out[((size_t)n * CO + co) * NPIX + p] = o;
        }
    }
}

// ---------------------------------------------------------------------------
// Fused postprocessing (reads NCHW heat/off)
// ---------------------------------------------------------------------------
__global__ __launch_bounds__(256) void postproc_k(
    const float* __restrict__ heat, const float* __restrict__ off,
    const float* __restrict__ alpha_p, const float* __restrict__ fusion_p,
    float* __restrict__ fw_out, float* __restrict__ coords_out,
    float* __restrict__ scores_out)
{
    __shared__ float r0[256], r1[256], r2[256];
    const int bk  = blockIdx.x;
    const int tid = threadIdx.x;
    const float* hm = heat + (size_t)bk * NPIX;

    float lm = -1e30f;
#pragma unroll
    for (int i = 0; i < 16; i++) lm = fmaxf(lm, hm[tid + i * 256]);
    r0[tid] = lm;
    __syncthreads();
    for (int s = 128; s > 0; s >>= 1) {
        if (tid < s) r0[tid] = fmaxf(r0[tid], r0[tid + s]);
        __syncthreads();
    }
    const float m = r0[0];
    __syncthreads();

    float se = 0.f, sx = 0.f, sy = 0.f;
#pragma unroll
    for (int i = 0; i < 16; i++) {
        const int idx = tid + i * 256;
        const float e = expf(hm[idx] - m);
        se += e;
        sx += e * (float)(idx & 63);
        sy += e * (float)(idx >> 6);
    }
    r0[tid] = se; r1[tid] = sx; r2[tid] = sy;
    __syncthreads();
    for (int s = 128; s > 0; s >>= 1) {
        if (tid < s) {
            r0[tid] += r0[tid + s];
            r1[tid] += r1[tid + s];
            r2[tid] += r2[tid + s];
        }
        __syncthreads();
    }

    if (tid == 0) {
        const float inv = 1.f / r0[0];
        const float xc = r1[0] * inv;
        const float yc = r2[0] * inv;

        const int px = (int)rintf(fminf(fmaxf(xc, 0.f), 63.f));
        const int py = (int)rintf(fminf(fmaxf(yc, 0.f), 63.f));
        int pxs[5], pys[5]; bool okx[5], oky[5];
#pragma unroll
        for (int i = 0; i < 5; i++) {
            const int xs = px - 2 + i; okx[i] = (xs >= 0 && xs < WW); pxs[i] = min(max(xs, 0), 63);
            const int ys = py - 2 + i; oky[i] = (ys >= 0 && ys < HH); pys[i] = min(max(ys, 0), 63);
        }
        float pv[25];
        float pm = -1e30f;
        for (int j = 0; j < 5; j++)
            for (int i = 0; i < 5; i++) {
                const float v = hm[pys[j] * WW + pxs[i]];
                pv[j * 5 + i] = v;
                if (okx[i] && oky[j]) pm = fmaxf(pm, v);
            }
        float ws = 0.f, rx = 0.f, ry = 0.f;
        for (int j = 0; j < 5; j++)
            for (int i = 0; i < 5; i++)
                if (okx[i] && oky[j]) {
                    const float e = expf(pv[j * 5 + i] - pm);
                    ws += e;
                    rx += e * (float)pxs[i];
                    ry += e * (float)pys[j];
                }
        rx /= ws; ry /= ws;

        const float a   = 1.f / (1.f + expf(-alpha_p[0]));
        const float fwv = 1.f / (1.f + expf(-fusion_p[0]));
        float cx = a * xc + (1.f - a) * rx;
        float cy = a * yc + (1.f - a) * ry;

        const float ix = fminf(fmaxf(cx, 0.f), 63.f);
        const float iy = fminf(fmaxf(cy, 0.f), 63.f);
        const float x0f = floorf(ix), y0f = floorf(iy);
        const float wx = ix - x0f, wy = iy - y0f;
        const int x0 = min(max((int)x0f, 0), 63);
        const int y0 = min(max((int)y0f, 0), 63);
        const int x1 = min(x0 + 1, 63);
        const int y1 = min(y0 + 1, 63);
        const float* ob = off + (size_t)bk * 2 * NPIX;
        float sv[2];
#pragma unroll
        for (int ch = 0; ch < 2; ch++) {
            const float* o = ob + ch * NPIX;
            const float v00 = o[y0 * WW + x0], v01 = o[y0 * WW + x1];
            const float v10 = o[y1 * WW + x0], v11 = o[y1 * WW + x1];
            sv[ch] = (1.f - wy) * ((1.f - wx) * v00 + wx * v01)
                   + wy * ((1.f - wx) * v10 + wx * v11);
        }
        cx += fwv * sv[0];
        cy += fwv * sv[1];

        coords_out[bk * 2 + 0] = cx;
        coords_out[bk * 2 + 1] = cy;
        scores_out[bk] = m;
        if (bk == 0) fw_out[0] = fwv;
    }
}

// ---------------------------------------------------------------------------
extern "C" void kernel_launch(void* const* d_in, const int* in_sizes, int n_in,
                              void* d_out, int out_size)
{
    const float* x    = (const float*)d_in[0];
    const float* w_s1 = (const float*)d_in[1];
    const float* g_s1 = (const float*)d_in[2];
    const float* b_s1 = (const float*)d_in[3];
    const float* w_s2 = (const float*)d_in[4];
    const float* g_s2 = (const float*)d_in[5];
    const float* b_s2 = (const float*)d_in[6];
    const float* w_h1 = (const float*)d_in[7];
    const float* g_h1 = (const float*)d_in[8];
    const float* b_h1 = (const float*)d_in[9];
    const float* w_h2 = (const float*)d_in[10];
    const float* c_h2 = (const float*)d_in[11];
    const float* w_o1 = (const float*)d_in[12];
    const float* g_o1 = (const float*)d_in[13];
    const float* b_o1 = (const float*)d_in[14];
    const float* w_o2 = (const float*)d_in[15];
    const float* c_o2 = (const float*)d_in[16];
    const float* w_v1 = (const float*)d_in[17];
    const float* g_v1 = (const float*)d_in[18];
    const float* b_v1 = (const float*)d_in[19];
    const float* w_v2 = (const float*)d_in[20];
    const float* c_v2 = (const float*)d_in[21];
    const float* alpha  = (const float*)d_in[22];
    const float* fusion = (const float*)d_in[23];

    float* out    = (float*)d_out;
    float* heat   = out;
    float* offp   = out + 2228224;
    float* varp   = out + 6684672;
    float* fwp    = out + 8912896;
    float* coords = out + 8912897;
    float* scores = out + 8913985;

    ushort_t *xh, *xl, *ah, *al, *sh, *sl, *th, *tl, *wh, *wl;
    cudaGetSymbolAddress((void**)&xh, g_xh);
    cudaGetSymbolAddress((void**)&xl, g_xl);
    cudaGetSymbolAddress((void**)&ah, g_ah);
    cudaGetSymbolAddress((void**)&al, g_al);
    cudaGetSymbolAddress((void**)&sh, g_sh);
    cudaGetSymbolAddress((void**)&sl, g_sl);
    cudaGetSymbolAddress((void**)&th, g_th);
    cudaGetSymbolAddress((void**)&tl, g_tl);
    cudaGetSymbolAddress((void**)&wh, g_wh);
    cudaGetSymbolAddress((void**)&wl, g_wl);

    // stems (2-pass): stage = 2*16KB A + 32KB B = 64KB; 3 stages = 192KB
    // heads (1-pass): conv256 stage = 16KB A + 32KB B = 48KB; 3 stages = 144KB
    //                 conv128 stage = 32KB A + 16KB B = 48KB; 3 stages = 144KB
    const int SMEM256_2P = 3 * (2 * 16384 + 32768);
    const int SMEM256_1P = 3 * (16384 + 32768);
    const int SMEM128_1P = 3 * (32768 + 16384);
    cudaFuncSetAttribute(conv3x3_mma<256, 2, 3>,
        cudaFuncAttributeMaxDynamicSharedMemorySize, SMEM256_2P);
    cudaFuncSetAttribute(conv3x3_mma<256, 1, 3>,
        cudaFuncAttributeMaxDynamicSharedMemorySize, SMEM256_1P);
    cudaFuncSetAttribute(conv3x3_mma<128, 1, 3>,
        cudaFuncAttributeMaxDynamicSharedMemorySize, SMEM128_1P);

    const size_t O_S1 = 0, O_S2 = 589824, O_H1 = 1179648, O_O1 = 1769472, O_V1 = 2359296;

    dim3 blk(256);
    dim3 cblk(256);
    dim3 g256(32, BATCH);   // M=128 pixel tiles
    dim3 g128(16, BATCH);   // M=256 pixel tiles

    // prep
    nchw2nhwc_split<<<dim3(1024, BATCH), blk>>>(x, xh, xl);
    wprep<<<2304, blk>>>(w_s1, wh + O_S1, wl + O_S1, 256);
    wprep<<<2304, blk>>>(w_s2, wh + O_S2, wl + O_S2, 256);
    wprep<<<2304, blk>>>(w_h1, wh + O_H1, wl + O_H1, 256);
    wprep<<<2304, blk>>>(w_o1, wh + O_O1, wl + O_O1, 256);

    // stem: 2-pass (exact activations x fp16 weights)
    conv3x3_mma<256, 2, 3><<<g256, cblk, SMEM256_2P>>>(xh, xl, wh + O_S1, wl + O_S1, g_s1, b_s1, ah, al);
    wprep<<<1152, blk>>>(w_v1, wh + O_V1, wl + O_V1, 128);
    conv3x3_mma<256, 2, 3><<<g256, cblk, SMEM256_2P>>>(ah, al, wh + O_S2, wl + O_S2, g_s2, b_s2, sh, sl);

    // heatmap head: 1-pass conv
    conv3x3_mma<256, 1, 3><<<g256, cblk, SMEM256_1P>>>(sh, sl, wh + O_H1, wl + O_H1, g_h1, b_h1, th, tl);
    conv1x1_k<256, 17, 4, false><<<128, blk>>>(th, tl, w_h2, c_h2, heat);

    // offset head: 1-pass conv
    conv3x3_mma<256, 1, 3><<<g256, cblk, SMEM256_1P>>>(sh, sl, wh + O_O1, wl + O_O1, g_o1, b_o1, th, tl);
    conv1x1_k<256, 34, 2, false><<<256, blk>>>(th, tl, w_o2, c_o2, offp);

    // variance head: 1-pass conv
    conv3x3_mma<128, 1, 3><<<g128, cblk, SMEM128_1P>>>(sh, sl, wh + O_V1, wl + O_V1, g_v1, b_v1, th, tl);
    conv1x1_k<128, 17, 4, true><<<128, blk>>>(th, tl, w_v2, c_v2, varp);

    // fused soft-argmax + refine + offset sampling
    postproc_k<<<BATCH * KPTS, blk>>>(heat, offp, alpha, fusion, fwp, coords, scores);
}